// round 12
// baseline (speedup 1.0000x reference)
#include <cuda_runtime.h>
#include <cuda_fp16.h>
#include <cstdint>

#define NPTS 200000
#define MPIL 30000
#define BATCH 2
#define GS 256
#define GS2 128
#define C1 64
#define C2 128

// ---------------- scratch ----------------
__device__ __align__(16) __half g_a0[BATCH*GS*GS*C1];
__device__ __align__(16) __half g_a1[BATCH*GS*GS*C1];   // also reused as fp16 xb2 plane
__device__ __align__(16) __half g_a2[BATCH*GS*GS*C1];
__device__ __align__(16) __half g_a3[BATCH*GS*GS*C1];
__device__ __align__(16) __half g_a4[BATCH*GS2*GS2*C2];
__device__ __align__(16) __half g_a5[BATCH*GS2*GS2*C2];
__device__ __align__(16) __half g_xb2h[BATCH*GS2*GS2*C2];
__device__ __align__(16) float g_x1 [BATCH*GS*GS*C1];
__device__ __align__(16) float g_x2 [BATCH*GS2*GS2*C2];
__device__ __align__(16) float g_xb2[BATCH*GS2*GS2*C2];
__device__ __align__(16) float g_h0  [NPTS*16];
__device__ __align__(16) float g_hmax[MPIL*16];
__device__ __align__(16) float g_fv  [MPIL*64];
__device__ __align__(16) float g_occ [BATCH*GS*GS];
__device__ __align__(16) float g_occ1[BATCH*GS*GS];
__device__ __align__(16) float g_occ2[BATCH*GS2*GS2];

// B-fragment store: [tap][chunk][ntile] blocks of 32 uint2 (fp16 frags)
#define FOFF1 0
#define FOFF2 (FOFF1 + 9216)
#define FOFF3 (FOFF2 + 9216)
#define FOFF4 (FOFF3 + 9216)
#define FOFF5 (FOFF4 + 18432)
#define FOFF6 (FOFF5 + 36864)
#define FTOT  (FOFF6 + 36864)
__device__ __align__(16) uint2 g_wfrag[FTOT];

// ---------------- helpers ----------------
__device__ __forceinline__ uint32_t smem_u32(const void* p) {
    uint32_t a;
    asm("{ .reg .u64 t; cvta.to.shared.u64 t, %1; cvt.u32.u64 %0, t; }" : "=r"(a) : "l"(p));
    return a;
}
__device__ __forceinline__ uint32_t pack_h2(float f0, float f1) {
    uint32_t r;
    asm("cvt.rn.f16x2.f32 %0, %1, %2;" : "=r"(r) : "f"(f1), "f"(f0));
    return r;
}
__device__ __forceinline__ void mma16816(float* c, const uint32_t* a,
                                         uint32_t b0, uint32_t b1) {
    asm volatile("mma.sync.aligned.m16n8k16.row.col.f32.f16.f16.f32 "
        "{%0,%1,%2,%3}, {%4,%5,%6,%7}, {%8,%9}, {%0,%1,%2,%3};"
        : "+f"(c[0]), "+f"(c[1]), "+f"(c[2]), "+f"(c[3])
        : "r"(a[0]), "r"(a[1]), "r"(a[2]), "r"(a[3]), "r"(b0), "r"(b1));
}
__device__ __forceinline__ void ldsm_x4(uint32_t& r0, uint32_t& r1, uint32_t& r2, uint32_t& r3,
                                        uint32_t saddr) {
    asm volatile("ldmatrix.sync.aligned.m8n8.x4.shared.b16 {%0,%1,%2,%3}, [%4];"
        : "=r"(r0), "=r"(r1), "=r"(r2), "=r"(r3) : "r"(saddr));
}
__device__ __forceinline__ void cp16(uint32_t dst, const void* src, bool ok) {
    int sz = ok ? 16 : 0;
    asm volatile("cp.async.cg.shared.global [%0], [%1], 16, %2;"
        :: "r"(dst), "l"(src), "r"(sz) : "memory");
}
__device__ __forceinline__ void cp_commit() {
    asm volatile("cp.async.commit_group;" ::: "memory");
}
template <int N>
__device__ __forceinline__ void cp_wait() {
    asm volatile("cp.async.wait_group %0;" :: "n"(N) : "memory");
}

// ---------------- merged zero ----------------
__global__ void zero_all_kernel(uint4* p0, int n0, uint4* p1, int n1,
                                uint4* p2, int n2, uint4* p3, int n3) {
    int i = blockIdx.x * blockDim.x + threadIdx.x;
    uint4 z = make_uint4(0u, 0u, 0u, 0u);
    if (i < n0) p0[i] = z;
    i -= n0;
    if (i >= 0 && i < n1) p1[i] = z;
    i -= n1;
    if (i >= 0 && i < n2) p2[i] = z;
    i -= n2;
    if (i >= 0 && i < n3) p3[i] = z;
}

// ---------------- merged weight prep (all 6 layers) ----------------
__global__ void wprep_all_kernel(
    const float* w1p, const float* w2p, const float* w3p,
    const float* w4p, const float* w5p, const float* w6p,
    uint2* __restrict__ dst)
{
    int idx = blockIdx.x * blockDim.x + threadIdx.x;
    int layer, base;
    const float* w;
    int cin, cout, foff;
    if (idx < 9216)            { layer = 0; base = 0; }
    else if (idx < 18432)      { layer = 1; base = 9216; }
    else if (idx < 27648)      { layer = 2; base = 18432; }
    else if (idx < 46080)      { layer = 3; base = 27648; }
    else if (idx < 82944)      { layer = 4; base = 46080; }
    else if (idx < 119808)     { layer = 5; base = 82944; }
    else return;
    switch (layer) {
        case 0: w = w1p; cin = 64;  cout = 64;  foff = FOFF1; break;
        case 1: w = w2p; cin = 64;  cout = 64;  foff = FOFF2; break;
        case 2: w = w3p; cin = 64;  cout = 64;  foff = FOFF3; break;
        case 3: w = w4p; cin = 64;  cout = 128; foff = FOFF4; break;
        case 4: w = w5p; cin = 128; cout = 128; foff = FOFF5; break;
        default:w = w6p; cin = 128; cout = 128; foff = FOFF6; break;
    }
    int li = idx - base;
    int chunks = cin / 16;
    int nttot = cout / 8;
    int lane = li & 31;
    int t = li >> 5;
    int nt = t % nttot;
    int t2 = t / nttot;
    int ch = t2 % chunks;
    int tap = t2 / chunks;
    int n = nt * 8 + (lane >> 2);
    int k0 = (lane & 3) * 2;
    int cib = ch * 16;
    float w00 = w[((size_t)tap * cin + cib + k0)     * cout + n];
    float w01 = w[((size_t)tap * cin + cib + k0 + 1) * cout + n];
    float w10 = w[((size_t)tap * cin + cib + k0 + 8) * cout + n];
    float w11 = w[((size_t)tap * cin + cib + k0 + 9) * cout + n];
    uint2* blk = dst + foff + (size_t)((tap * chunks + ch) * nttot + nt) * 32;
    blk[lane] = make_uint2(pack_h2(w00, w01), pack_h2(w10, w11));
}

// ---------------- PFN layer 0 ----------------
__global__ __launch_bounds__(256) void pfn0_kernel(
    const float* __restrict__ feat, const int* __restrict__ inv,
    const float* __restrict__ w0, const float* __restrict__ g0, const float* __restrict__ b0,
    float* __restrict__ h0, float* __restrict__ hmax)
{
    __shared__ float sw[256];
    __shared__ float sg[16], sb[16];
    if (threadIdx.x < 256) sw[threadIdx.x] = w0[threadIdx.x];
    if (threadIdx.x < 16) { sg[threadIdx.x] = g0[threadIdx.x]; sb[threadIdx.x] = b0[threadIdx.x]; }
    __syncthreads();
    int i = blockIdx.x * 256 + threadIdx.x;
    if (i >= NPTS) return;
    float f[16];
    const float4* fp = reinterpret_cast<const float4*>(feat + (size_t)i * 16);
#pragma unroll
    for (int t = 0; t < 4; t++) {
        float4 v = fp[t];
        f[4*t]=v.x; f[4*t+1]=v.y; f[4*t+2]=v.z; f[4*t+3]=v.w;
    }
    float acc[16];
#pragma unroll
    for (int j = 0; j < 16; j++) acc[j] = 0.f;
#pragma unroll
    for (int c = 0; c < 16; c++) {
        float xv = f[c];
#pragma unroll
        for (int j = 0; j < 16; j++) acc[j] += xv * sw[c * 16 + j];
    }
    int seg = inv[i];
    float h[16];
#pragma unroll
    for (int j = 0; j < 16; j++) h[j] = fmaxf(acc[j] * sg[j] + sb[j], 0.f);
    float4* hp = reinterpret_cast<float4*>(h0 + (size_t)i * 16);
#pragma unroll
    for (int t = 0; t < 4; t++) hp[t] = make_float4(h[4*t], h[4*t+1], h[4*t+2], h[4*t+3]);
    int* hm = reinterpret_cast<int*>(hmax + (size_t)seg * 16);
#pragma unroll
    for (int j = 0; j < 16; j++)
        if (h[j] > 0.f) atomicMax(hm + j, __float_as_int(h[j]));
}

// ---------------- PFN layer 1 (split-N: 2 threads per point, 32 couts each) ----------------
__global__ __launch_bounds__(256) void pfn1_kernel(
    const int* __restrict__ inv,
    const float* __restrict__ w1, const float* __restrict__ g1, const float* __restrict__ b1,
    const float* __restrict__ h0, const float* __restrict__ hmax, float* __restrict__ fv)
{
    __shared__ float sw[32 * 64];
    __shared__ float sg[64], sb[64];
    for (int t = threadIdx.x; t < 2048; t += blockDim.x) sw[t] = w1[t];
    if (threadIdx.x < 64) { sg[threadIdx.x] = g1[threadIdx.x]; sb[threadIdx.x] = b1[threadIdx.x]; }
    __syncthreads();
    int gt = blockIdx.x * 256 + threadIdx.x;
    int i = gt >> 1;
    int hh = gt & 1;              // which 32-cout half
    if (i >= NPTS) return;
    int seg = inv[i];
    float x[32];
    const float4* hp = reinterpret_cast<const float4*>(h0 + (size_t)i * 16);
    const float4* mp = reinterpret_cast<const float4*>(hmax + (size_t)seg * 16);
#pragma unroll
    for (int t = 0; t < 4; t++) {
        float4 v = hp[t];
        x[4*t]=v.x; x[4*t+1]=v.y; x[4*t+2]=v.z; x[4*t+3]=v.w;
        float4 u = mp[t];
        x[16+4*t]=u.x; x[16+4*t+1]=u.y; x[16+4*t+2]=u.z; x[16+4*t+3]=u.w;
    }
    const int cb = hh * 32;
    float acc[32];
#pragma unroll
    for (int j = 0; j < 32; j++) acc[j] = 0.f;
#pragma unroll
    for (int c = 0; c < 32; c++) {
        float xv = x[c];
        const float4* wr = reinterpret_cast<const float4*>(&sw[c * 64 + cb]);
#pragma unroll
        for (int k = 0; k < 8; k++) {
            float4 w = wr[k];
            acc[4*k] += xv*w.x; acc[4*k+1] += xv*w.y;
            acc[4*k+2] += xv*w.z; acc[4*k+3] += xv*w.w;
        }
    }
    int* fp = reinterpret_cast<int*>(fv + (size_t)seg * 64 + cb);
#pragma unroll
    for (int j = 0; j < 32; j++) {
        float v = fmaxf(acc[j] * sg[cb + j] + sb[cb + j], 0.f);
        if (v > 0.f) atomicMax(fp + j, __float_as_int(v));
    }
}

// ---------------- scatter pillars -> fp16 plane + occ ----------------
__global__ void scatter_kernel(const int* __restrict__ unq, const float* __restrict__ fv,
                               __half* __restrict__ ah, float* __restrict__ occ)
{
    int idx = blockIdx.x * blockDim.x + threadIdx.x;
    if (idx >= MPIL * 8) return;
    int m = idx >> 3, k = idx & 7;
    int bb = unq[m*3], yy = unq[m*3+1], xx = unq[m*3+2];
    const float4* fp = reinterpret_cast<const float4*>(fv) + m * 16 + 2 * k;
    float4 a = fp[0], b = fp[1];
    uint4 hw;
    hw.x = pack_h2(a.x, a.y);
    hw.y = pack_h2(a.z, a.w);
    hw.z = pack_h2(b.x, b.y);
    hw.w = pack_h2(b.z, b.w);
    size_t pix = ((size_t)(bb * GS + yy) * GS + xx) * 64;
    reinterpret_cast<uint4*>(ah + pix)[k] = hw;
    if (k == 0) occ[(bb * GS + yy) * GS + xx] = 1.0f;
}

// ---------------- occupancy dilations ----------------
__global__ void occ1_kernel(const float* __restrict__ occ, float* __restrict__ occ1) {
    int idx = blockIdx.x * blockDim.x + threadIdx.x;
    if (idx >= BATCH * GS * GS) return;
    int x = idx % GS, y = (idx / GS) % GS, b = idx / (GS * GS);
    float m = 0.f;
#pragma unroll
    for (int dy = -1; dy <= 1; dy++)
#pragma unroll
        for (int dx = -1; dx <= 1; dx++) {
            int yy = y + dy, xx = x + dx;
            if (yy >= 0 && yy < GS && xx >= 0 && xx < GS)
                m = fmaxf(m, occ[(b * GS + yy) * GS + xx]);
        }
    occ1[idx] = m;
}
__global__ void occ2_kernel(const float* __restrict__ occ1, float* __restrict__ occ2) {
    int idx = blockIdx.x * blockDim.x + threadIdx.x;
    if (idx >= BATCH * GS2 * GS2) return;
    int x = idx % GS2, y = (idx / GS2) % GS2, b = idx / (GS2 * GS2);
    float m = 0.f;
#pragma unroll
    for (int dy = -1; dy <= 1; dy++)
#pragma unroll
        for (int dx = -1; dx <= 1; dx++) {
            int yy = 2 * y + dy, xx = 2 * x + dx;
            if (yy >= 0 && yy < GS && xx >= 0 && xx < GS)
                m = fmaxf(m, occ1[(b * GS + yy) * GS + xx]);
        }
    occ2[idx] = m;
}

// ---------------- HMMA conv3x3 (fp16), cp.async pipelined, ldmatrix A ----------------
template <int CIN, int COUT, int STRIDE, int TM, int BUFS, bool RESID, bool OUTF32, bool PLANES>
__global__ __launch_bounds__(256) void conv_mma(
    const __half* __restrict__ in,
    const uint2* __restrict__ wfrag,
    const float* __restrict__ gm, const float* __restrict__ bt,
    const float* __restrict__ mask, const float* __restrict__ resid,
    float* __restrict__ outf, __half* __restrict__ outh,
    int IH, int IW, int OH, int OW)
{
    constexpr int CHUNKS = CIN / 16;
    constexpr int NTTOT = COUT / 8;
    constexpr int NT = COUT / 16;
    constexpr int R = (TM - 1) * STRIDE + 3;
    constexpr int PXW = 64 * STRIDE + 2;
    constexpr int NV = R * PXW * 2;

    extern __shared__ __align__(16) char smem_raw[];
    __half* s_in = reinterpret_cast<__half*>(smem_raw);
    auto sidx = [&](int buf, int ry, int px) {
        return ((buf * R + ry) * PXW + px) * 16;
    };

    const int tid = threadIdx.x;
    const int wid = tid >> 5, lane = tid & 31;
    const int mwarp = wid >> 1, nwarp = wid & 1;
    const int g = lane >> 2, q = lane & 3;
    const int y0 = blockIdx.y * TM;
    const int xb = blockIdx.x * 64;
    const int bb = blockIdx.z;

    const int mat = lane >> 3;
    const int mrow = (mat & 1) * 8 + (lane & 7);
    const int koff = (mat >> 1) * 8;
    const int pxbase = (mwarp * 16 + mrow) * STRIDE;
    const uint32_t sb32 = smem_u32(s_in);

    float acc[TM][NT][4];
#pragma unroll
    for (int r = 0; r < TM; r++)
#pragma unroll
        for (int nt = 0; nt < NT; nt++)
#pragma unroll
            for (int j = 0; j < 4; j++) acc[r][nt][j] = 0.f;

    auto stage = [&](int ch, int buf) {
#pragma unroll 1
        for (int i = tid; i < NV; i += 256) {
            int half = i & 1;
            int r2 = i >> 1;
            int px = r2 % PXW;
            int ry = r2 / PXW;
            int iy = y0 * STRIDE + ry - 1;
            int ix = xb * STRIDE + px - 1;
            bool ok = (iy >= 0) && (iy < IH) && (ix >= 0) && (ix < IW);
            const void* src = ok
                ? (const void*)(in + ((size_t)(bb * IH + iy) * IW + ix) * CIN + ch * 16 + half * 8)
                : (const void*)in;
            cp16(smem_u32(s_in + sidx(buf, ry, px) + half * 8), src, ok);
        }
        cp_commit();
    };

    stage(0, 0);

#pragma unroll 1
    for (int ch = 0; ch < CHUNKS; ch++) {
        const int buf = (BUFS == 3) ? (ch % 3) : (ch & 1);
        if (ch + 1 < CHUNKS) {
            stage(ch + 1, (BUFS == 3) ? ((ch + 1) % 3) : ((ch + 1) & 1));
            cp_wait<1>();
        } else {
            cp_wait<0>();
        }
        __syncthreads();
#pragma unroll
        for (int ky = 0; ky < 3; ky++) {
#pragma unroll
            for (int kx = 0; kx < 3; kx++) {
                const uint2* bbase = wfrag
                    + (size_t)(((ky * 3 + kx) * CHUNKS + ch) * NTTOT + nwarp * NT) * 32;
                uint2 bh[NT];
#pragma unroll
                for (int nt = 0; nt < NT; nt++) bh[nt] = __ldg(bbase + nt * 32 + lane);
                uint32_t A[TM][4];
#pragma unroll
                for (int r = 0; r < TM; r++) {
                    const int row = r * STRIDE + ky;
                    uint32_t ad = sb32 + (uint32_t)((((buf * R + row) * PXW) + pxbase + kx) * 16 + koff) * 2;
                    ldsm_x4(A[r][0], A[r][1], A[r][2], A[r][3], ad);
                }
#pragma unroll
                for (int r = 0; r < TM; r++)
#pragma unroll
                    for (int nt = 0; nt < NT; nt++)
                        mma16816(acc[r][nt], A[r], bh[nt].x, bh[nt].y);
            }
        }
        if (BUFS == 2) __syncthreads();
    }

    // epilogue
    const int xa = xb + mwarp * 16 + g;
#pragma unroll
    for (int r = 0; r < TM; r++) {
        const int y = y0 + r;
        const size_t pa = (size_t)(bb * OH + y) * OW + xa;
        const size_t pb = pa + 8;
        const float mva = mask[pa];
        const float mvb = mask[pb];
#pragma unroll
        for (int nt = 0; nt < NT; nt++) {
            const int co = nwarp * (COUT / 2) + nt * 8 + 2 * q;
            const float g0 = __ldg(gm + co), g1 = __ldg(gm + co + 1);
            const float b0 = __ldg(bt + co), b1 = __ldg(bt + co + 1);
            float v0 = acc[r][nt][0] * g0 + b0;
            float v1 = acc[r][nt][1] * g1 + b1;
            float v2 = acc[r][nt][2] * g0 + b0;
            float v3 = acc[r][nt][3] * g1 + b1;
            if (RESID) {
                float2 ra = *reinterpret_cast<const float2*>(resid + pa * COUT + co);
                float2 rb = *reinterpret_cast<const float2*>(resid + pb * COUT + co);
                v0 = fmaxf(ra.x + v0 * mva, 0.f);
                v1 = fmaxf(ra.y + v1 * mva, 0.f);
                v2 = fmaxf(rb.x + v2 * mvb, 0.f);
                v3 = fmaxf(rb.y + v3 * mvb, 0.f);
            } else {
                v0 = fmaxf(v0, 0.f) * mva;
                v1 = fmaxf(v1, 0.f) * mva;
                v2 = fmaxf(v2, 0.f) * mvb;
                v3 = fmaxf(v3, 0.f) * mvb;
            }
            if (OUTF32) {
                *reinterpret_cast<float2*>(outf + pa * COUT + co) = make_float2(v0, v1);
                *reinterpret_cast<float2*>(outf + pb * COUT + co) = make_float2(v2, v3);
            }
            if (PLANES) {
                *reinterpret_cast<uint32_t*>(outh + pa * COUT + co) = pack_h2(v0, v1);
                *reinterpret_cast<uint32_t*>(outh + pb * COUT + co) = pack_h2(v2, v3);
            }
        }
    }
}

// ---------------- bilinear gather (fp16 feature plane) ----------------
__global__ __launch_bounds__(256) void gather_kernel(
    const float* __restrict__ feat, const int* __restrict__ unq, const int* __restrict__ inv,
    const __half* __restrict__ xh, float* __restrict__ out)
{
    int gwarp = (blockIdx.x * blockDim.x + threadIdx.x) >> 5;
    int lane = threadIdx.x & 31;
    if (gwarp >= NPTS) return;
    int i = gwarp;
    float f0 = __ldg(feat + (size_t)i * 16);
    float f1 = __ldg(feat + (size_t)i * 16 + 1);
    float px = ((f0 + 51.2f) / 0.4f) * 0.5f;
    float py = ((f1 + 51.2f) / 0.4f) * 0.5f;
    int seg = __ldg(inv + i);
    int bb = __ldg(unq + seg * 3);
    int fx = (int)floorf(px), fy = (int)floorf(py);
    int x0 = min(max(fx, 0), GS2 - 1), x1 = min(max(fx + 1, 0), GS2 - 1);
    int y0 = min(max(fy, 0), GS2 - 1), y1 = min(max(fy + 1, 0), GS2 - 1);
    float x0f = (float)x0, x1f = (float)x1, y0f = (float)y0, y1f = (float)y1;
    float wa = (x1f - px) * (y1f - py);
    float wb = (x1f - px) * (py - y0f);
    float wc = (px - x0f) * (y1f - py);
    float wd = (px - x0f) * (py - y0f);
    const uint2* A  = reinterpret_cast<const uint2*>(xh + ((size_t)(bb*GS2+y0)*GS2+x0)*C2) + lane;
    const uint2* Bp = reinterpret_cast<const uint2*>(xh + ((size_t)(bb*GS2+y1)*GS2+x0)*C2) + lane;
    const uint2* Cp = reinterpret_cast<const uint2*>(xh + ((size_t)(bb*GS2+y0)*GS2+x1)*C2) + lane;
    const uint2* D  = reinterpret_cast<const uint2*>(xh + ((size_t)(bb*GS2+y1)*GS2+x1)*C2) + lane;
    uint2 ua = __ldg(A), ub = __ldg(Bp), uc = __ldg(Cp), ud = __ldg(D);
    float2 a0 = __half22float2(*reinterpret_cast<__half2*>(&ua.x));
    float2 a1 = __half22float2(*reinterpret_cast<__half2*>(&ua.y));
    float2 b0 = __half22float2(*reinterpret_cast<__half2*>(&ub.x));
    float2 b1 = __half22float2(*reinterpret_cast<__half2*>(&ub.y));
    float2 c0 = __half22float2(*reinterpret_cast<__half2*>(&uc.x));
    float2 c1 = __half22float2(*reinterpret_cast<__half2*>(&uc.y));
    float2 d0 = __half22float2(*reinterpret_cast<__half2*>(&ud.x));
    float2 d1 = __half22float2(*reinterpret_cast<__half2*>(&ud.y));
    float4 r;
    r.x = a0.x*wa + b0.x*wb + c0.x*wc + d0.x*wd;
    r.y = a0.y*wa + b0.y*wb + c0.y*wc + d0.y*wd;
    r.z = a1.x*wa + b1.x*wb + c1.x*wc + d1.x*wd;
    r.w = a1.y*wa + b1.y*wb + c1.y*wc + d1.y*wd;
    reinterpret_cast<float4*>(out + (size_t)i * C2)[lane] = r;
}

// ---------------- launch ----------------
extern "C" void kernel_launch(void* const* d_in, const int* in_sizes, int n_in,
                              void* d_out, int out_size)
{
    const float* feat = (const float*)d_in[0];
    const int* unq = (const int*)d_in[1];
    const int* inv = (const int*)d_in[2];
    int wb = (in_sizes[3] == 1) ? 4 : 3;
    const float* W[24];
    for (int i = 0; i < 24; i++) W[i] = (const float*)d_in[wb + i];
    float* out = (float*)d_out;

    float *p_h0, *p_hmax, *p_fv, *p_x1, *p_x2, *p_xb2, *p_occ, *p_occ1, *p_occ2;
    __half *a0, *a1, *a2, *a3, *a4, *a5, *xb2h;
    uint2* p_wf;
    cudaGetSymbolAddress((void**)&p_h0, g_h0);
    cudaGetSymbolAddress((void**)&p_hmax, g_hmax);
    cudaGetSymbolAddress((void**)&p_fv, g_fv);
    cudaGetSymbolAddress((void**)&p_x1, g_x1);
    cudaGetSymbolAddress((void**)&p_x2, g_x2);
    cudaGetSymbolAddress((void**)&p_xb2, g_xb2);
    cudaGetSymbolAddress((void**)&p_occ, g_occ);
    cudaGetSymbolAddress((void**)&p_occ1, g_occ1);
    cudaGetSymbolAddress((void**)&p_occ2, g_occ2);
    cudaGetSymbolAddress((void**)&a0, g_a0);
    cudaGetSymbolAddress((void**)&a1, g_a1);
    cudaGetSymbolAddress((void**)&a2, g_a2);
    cudaGetSymbolAddress((void**)&a3, g_a3);
    cudaGetSymbolAddress((void**)&a4, g_a4);
    cudaGetSymbolAddress((void**)&a5, g_a5);
    cudaGetSymbolAddress((void**)&xb2h, g_xb2h);
    cudaGetSymbolAddress((void**)&p_wf, g_wfrag);

    // merged zero: a0 (fp16 plane), hmax, fv, occ
    const int N0 = BATCH*GS*GS*C1*2/16;
    const int N1 = MPIL*16*4/16;
    const int N2 = MPIL*64*4/16;
    const int N3 = BATCH*GS*GS*4/16;
    zero_all_kernel<<<(N0+N1+N2+N3 + 255)/256, 256>>>(
        (uint4*)a0, N0, (uint4*)p_hmax, N1, (uint4*)p_fv, N2, (uint4*)p_occ, N3);

    wprep_all_kernel<<<(119808 + 255)/256, 256>>>(
        W[6], W[9], W[12], W[15], W[18], W[21], p_wf);

    pfn0_kernel<<<(NPTS + 255)/256, 256>>>(feat, inv, W[0], W[1], W[2], p_h0, p_hmax);
    pfn1_kernel<<<(NPTS*2 + 255)/256, 256>>>(inv, W[3], W[4], W[5], p_h0, p_hmax, p_fv);
    scatter_kernel<<<(MPIL*8 + 255)/256, 256>>>(unq, p_fv, a0, p_occ);
    occ1_kernel<<<(BATCH*GS*GS + 255)/256, 256>>>(p_occ, p_occ1);
    occ2_kernel<<<(BATCH*GS2*GS2 + 255)/256, 256>>>(p_occ1, p_occ2);

    // dynamic smem: BUFS * R * PXW * 16 halves * 2B
    const int S13 = 3 * 6 * 66 * 16 * 2;   // 38016 (TM=4, s1, BUFS=3)
    const int S4  = 2 * 5 * 130 * 16 * 2;  // 41600 (TM=2, s2, BUFS=2)
    const int S56 = 3 * 4 * 66 * 16 * 2;   // 25344 (TM=2, s1, BUFS=3)
    cudaFuncSetAttribute(conv_mma<64,64,1,4,3,false,true,true>,   cudaFuncAttributeMaxDynamicSharedMemorySize, S13);
    cudaFuncSetAttribute(conv_mma<64,64,1,4,3,false,false,true>,  cudaFuncAttributeMaxDynamicSharedMemorySize, S13);
    cudaFuncSetAttribute(conv_mma<64,64,1,4,3,true,false,true>,   cudaFuncAttributeMaxDynamicSharedMemorySize, S13);
    cudaFuncSetAttribute(conv_mma<64,128,2,2,2,false,true,true>,  cudaFuncAttributeMaxDynamicSharedMemorySize, S4);
    cudaFuncSetAttribute(conv_mma<128,128,1,2,3,false,false,true>,cudaFuncAttributeMaxDynamicSharedMemorySize, S56);
    cudaFuncSetAttribute(conv_mma<128,128,1,2,3,true,false,true>, cudaFuncAttributeMaxDynamicSharedMemorySize, S56);

    dim3 blk(256);
    // L1-3: 64->64 s1, TM=4, BUFS=3: grid (4, 64, 2)
    dim3 g1(GS/64, GS/4, BATCH);
    conv_mma<64,64,1,4,3,false,true,true><<<g1, blk, S13>>>(
        a0, p_wf + FOFF1, W[7], W[8], p_occ1, nullptr, p_x1, a1, GS, GS, GS, GS);
    conv_mma<64,64,1,4,3,false,false,true><<<g1, blk, S13>>>(
        a1, p_wf + FOFF2, W[10], W[11], p_occ1, nullptr, nullptr, a2, GS, GS, GS, GS);
    conv_mma<64,64,1,4,3,true,false,true><<<g1, blk, S13>>>(
        a2, p_wf + FOFF3, W[13], W[14], p_occ1, p_x1, nullptr, a3, GS, GS, GS, GS);

    // L4: 64->128 s2, TM=2, BUFS=2: grid (2, 64, 2)
    dim3 g2(GS2/64, GS2/2, BATCH);
    conv_mma<64,128,2,2,2,false,true,true><<<g2, blk, S4>>>(
        a3, p_wf + FOFF4, W[16], W[17], p_occ2, nullptr, p_x2, a4, GS, GS, GS2, GS2);
    // L5: 128->128 s1
    conv_mma<128,128,1,2,3,false,false,true><<<g2, blk, S56>>>(
        a4, p_wf + FOFF5, W[19], W[20], p_occ2, nullptr, nullptr, a5, GS2, GS2, GS2, GS2);
    // L6: 128->128 s1 + residual, emit fp16 plane for gather (no fp32 write needed)
    conv_mma<128,128,1,2,3,true,false,true><<<g2, blk, S56>>>(
        a5, p_wf + FOFF6, W[22], W[23], p_occ2, p_x2, nullptr, xb2h, GS2, GS2, GS2, GS2);

    gather_kernel<<<(NPTS*32 + 255)/256, 256>>>(feat, unq, inv, xb2h, out);
    (void)n_in; (void)out_size; (void)p_xb2;
}

// round 13
// speedup vs baseline: 1.0574x; 1.0574x over previous
#include <cuda_runtime.h>
#include <cuda_fp16.h>
#include <cstdint>

#define NPTS 200000
#define MPIL 30000
#define BATCH 2
#define GS 256
#define GS2 128
#define C1 64
#define C2 128

// ---------------- scratch ----------------
__device__ __align__(16) __half g_a0[BATCH*GS*GS*C1];
__device__ __align__(16) __half g_a1[BATCH*GS*GS*C1];
__device__ __align__(16) __half g_a2[BATCH*GS*GS*C1];
__device__ __align__(16) __half g_a3[BATCH*GS*GS*C1];
__device__ __align__(16) __half g_a4[BATCH*GS2*GS2*C2];
__device__ __align__(16) __half g_a5[BATCH*GS2*GS2*C2];
__device__ __align__(16) __half g_xb2h[BATCH*GS2*GS2*C2];
__device__ __align__(16) float g_x1 [BATCH*GS*GS*C1];
__device__ __align__(16) float g_x2 [BATCH*GS2*GS2*C2];
__device__ __align__(16) float g_h0  [NPTS*16];
__device__ __align__(16) float g_hmax[MPIL*16];
__device__ __align__(16) float g_fv  [MPIL*64];
__device__ __align__(16) float g_occ [BATCH*GS*GS];
__device__ __align__(16) float g_occ1[BATCH*GS*GS];
__device__ __align__(16) float g_occ2[BATCH*GS2*GS2];

// B-fragment store: [tap][chunk][ntile] blocks of 32 uint2 (fp16 frags)
#define FOFF1 0
#define FOFF2 (FOFF1 + 9216)
#define FOFF3 (FOFF2 + 9216)
#define FOFF4 (FOFF3 + 9216)
#define FOFF5 (FOFF4 + 18432)
#define FOFF6 (FOFF5 + 36864)
#define FTOT  (FOFF6 + 36864)
__device__ __align__(16) uint2 g_wfrag[FTOT];

// ---------------- helpers ----------------
__device__ __forceinline__ uint32_t smem_u32(const void* p) {
    uint32_t a;
    asm("{ .reg .u64 t; cvta.to.shared.u64 t, %1; cvt.u32.u64 %0, t; }" : "=r"(a) : "l"(p));
    return a;
}
__device__ __forceinline__ uint32_t pack_h2(float f0, float f1) {
    uint32_t r;
    asm("cvt.rn.f16x2.f32 %0, %1, %2;" : "=r"(r) : "f"(f1), "f"(f0));
    return r;
}
__device__ __forceinline__ void mma16816(float* c, const uint32_t* a,
                                         uint32_t b0, uint32_t b1) {
    asm volatile("mma.sync.aligned.m16n8k16.row.col.f32.f16.f16.f32 "
        "{%0,%1,%2,%3}, {%4,%5,%6,%7}, {%8,%9}, {%0,%1,%2,%3};"
        : "+f"(c[0]), "+f"(c[1]), "+f"(c[2]), "+f"(c[3])
        : "r"(a[0]), "r"(a[1]), "r"(a[2]), "r"(a[3]), "r"(b0), "r"(b1));
}
__device__ __forceinline__ void ldsm_x4(uint32_t& r0, uint32_t& r1, uint32_t& r2, uint32_t& r3,
                                        uint32_t saddr) {
    asm volatile("ldmatrix.sync.aligned.m8n8.x4.shared.b16 {%0,%1,%2,%3}, [%4];"
        : "=r"(r0), "=r"(r1), "=r"(r2), "=r"(r3) : "r"(saddr));
}
__device__ __forceinline__ void cp16(uint32_t dst, const void* src, bool ok) {
    int sz = ok ? 16 : 0;
    asm volatile("cp.async.cg.shared.global [%0], [%1], 16, %2;"
        :: "r"(dst), "l"(src), "r"(sz) : "memory");
}
__device__ __forceinline__ void cp_commit() {
    asm volatile("cp.async.commit_group;" ::: "memory");
}
template <int N>
__device__ __forceinline__ void cp_wait() {
    asm volatile("cp.async.wait_group %0;" :: "n"(N) : "memory");
}

// ---------------- merged zero ----------------
__global__ void zero_all_kernel(uint4* p0, int n0, uint4* p1, int n1,
                                uint4* p2, int n2, uint4* p3, int n3) {
    int i = blockIdx.x * blockDim.x + threadIdx.x;
    uint4 z = make_uint4(0u, 0u, 0u, 0u);
    if (i < n0) p0[i] = z;
    i -= n0;
    if (i >= 0 && i < n1) p1[i] = z;
    i -= n1;
    if (i >= 0 && i < n2) p2[i] = z;
    i -= n2;
    if (i >= 0 && i < n3) p3[i] = z;
}

// ---------------- merged weight prep (all 6 layers) ----------------
__global__ void wprep_all_kernel(
    const float* w1p, const float* w2p, const float* w3p,
    const float* w4p, const float* w5p, const float* w6p,
    uint2* __restrict__ dst)
{
    int idx = blockIdx.x * blockDim.x + threadIdx.x;
    int layer, base;
    const float* w;
    int cin, cout, foff;
    if (idx < 9216)            { layer = 0; base = 0; }
    else if (idx < 18432)      { layer = 1; base = 9216; }
    else if (idx < 27648)      { layer = 2; base = 18432; }
    else if (idx < 46080)      { layer = 3; base = 27648; }
    else if (idx < 82944)      { layer = 4; base = 46080; }
    else if (idx < 119808)     { layer = 5; base = 82944; }
    else return;
    switch (layer) {
        case 0: w = w1p; cin = 64;  cout = 64;  foff = FOFF1; break;
        case 1: w = w2p; cin = 64;  cout = 64;  foff = FOFF2; break;
        case 2: w = w3p; cin = 64;  cout = 64;  foff = FOFF3; break;
        case 3: w = w4p; cin = 64;  cout = 128; foff = FOFF4; break;
        case 4: w = w5p; cin = 128; cout = 128; foff = FOFF5; break;
        default:w = w6p; cin = 128; cout = 128; foff = FOFF6; break;
    }
    int li = idx - base;
    int chunks = cin / 16;
    int nttot = cout / 8;
    int lane = li & 31;
    int t = li >> 5;
    int nt = t % nttot;
    int t2 = t / nttot;
    int ch = t2 % chunks;
    int tap = t2 / chunks;
    int n = nt * 8 + (lane >> 2);
    int k0 = (lane & 3) * 2;
    int cib = ch * 16;
    float w00 = w[((size_t)tap * cin + cib + k0)     * cout + n];
    float w01 = w[((size_t)tap * cin + cib + k0 + 1) * cout + n];
    float w10 = w[((size_t)tap * cin + cib + k0 + 8) * cout + n];
    float w11 = w[((size_t)tap * cin + cib + k0 + 9) * cout + n];
    uint2* blk = dst + foff + (size_t)((tap * chunks + ch) * nttot + nt) * 32;
    blk[lane] = make_uint2(pack_h2(w00, w01), pack_h2(w10, w11));
}

// ---------------- PFN layer 0 ----------------
__global__ __launch_bounds__(256) void pfn0_kernel(
    const float* __restrict__ feat, const int* __restrict__ inv,
    const float* __restrict__ w0, const float* __restrict__ g0, const float* __restrict__ b0,
    float* __restrict__ h0, float* __restrict__ hmax)
{
    __shared__ float sw[256];
    __shared__ float sg[16], sb[16];
    if (threadIdx.x < 256) sw[threadIdx.x] = w0[threadIdx.x];
    if (threadIdx.x < 16) { sg[threadIdx.x] = g0[threadIdx.x]; sb[threadIdx.x] = b0[threadIdx.x]; }
    __syncthreads();
    int i = blockIdx.x * 256 + threadIdx.x;
    if (i >= NPTS) return;
    float f[16];
    const float4* fp = reinterpret_cast<const float4*>(feat + (size_t)i * 16);
#pragma unroll
    for (int t = 0; t < 4; t++) {
        float4 v = fp[t];
        f[4*t]=v.x; f[4*t+1]=v.y; f[4*t+2]=v.z; f[4*t+3]=v.w;
    }
    float acc[16];
#pragma unroll
    for (int j = 0; j < 16; j++) acc[j] = 0.f;
#pragma unroll
    for (int c = 0; c < 16; c++) {
        float xv = f[c];
#pragma unroll
        for (int j = 0; j < 16; j++) acc[j] += xv * sw[c * 16 + j];
    }
    int seg = inv[i];
    float h[16];
#pragma unroll
    for (int j = 0; j < 16; j++) h[j] = fmaxf(acc[j] * sg[j] + sb[j], 0.f);
    float4* hp = reinterpret_cast<float4*>(h0 + (size_t)i * 16);
#pragma unroll
    for (int t = 0; t < 4; t++) hp[t] = make_float4(h[4*t], h[4*t+1], h[4*t+2], h[4*t+3]);
    int* hm = reinterpret_cast<int*>(hmax + (size_t)seg * 16);
#pragma unroll
    for (int j = 0; j < 16; j++)
        if (h[j] > 0.f) atomicMax(hm + j, __float_as_int(h[j]));
}

// ---------------- PFN layer 1 (R11 form: one thread per point, 64 couts) ----------------
__global__ __launch_bounds__(128) void pfn1_kernel(
    const int* __restrict__ inv,
    const float* __restrict__ w1, const float* __restrict__ g1, const float* __restrict__ b1,
    const float* __restrict__ h0, const float* __restrict__ hmax, float* __restrict__ fv)
{
    __shared__ float sw[32 * 64];
    __shared__ float sg[64], sb[64];
    for (int t = threadIdx.x; t < 2048; t += blockDim.x) sw[t] = w1[t];
    if (threadIdx.x < 64) { sg[threadIdx.x] = g1[threadIdx.x]; sb[threadIdx.x] = b1[threadIdx.x]; }
    __syncthreads();
    int i = blockIdx.x * blockDim.x + threadIdx.x;
    if (i >= NPTS) return;
    int seg = inv[i];
    float x[32];
    const float4* hp = reinterpret_cast<const float4*>(h0 + (size_t)i * 16);
    const float4* mp = reinterpret_cast<const float4*>(hmax + (size_t)seg * 16);
#pragma unroll
    for (int t = 0; t < 4; t++) {
        float4 v = hp[t];
        x[4*t]=v.x; x[4*t+1]=v.y; x[4*t+2]=v.z; x[4*t+3]=v.w;
        float4 u = mp[t];
        x[16+4*t]=u.x; x[16+4*t+1]=u.y; x[16+4*t+2]=u.z; x[16+4*t+3]=u.w;
    }
    float acc[64];
#pragma unroll
    for (int j = 0; j < 64; j++) acc[j] = 0.f;
#pragma unroll
    for (int c = 0; c < 32; c++) {
        float xv = x[c];
        const float4* wr = reinterpret_cast<const float4*>(&sw[c * 64]);
#pragma unroll
        for (int k = 0; k < 16; k++) {
            float4 w = wr[k];
            acc[4*k] += xv*w.x; acc[4*k+1] += xv*w.y;
            acc[4*k+2] += xv*w.z; acc[4*k+3] += xv*w.w;
        }
    }
    int* fp = reinterpret_cast<int*>(fv + (size_t)seg * 64);
#pragma unroll
    for (int j = 0; j < 64; j++) {
        float v = fmaxf(acc[j] * sg[j] + sb[j], 0.f);
        if (v > 0.f) atomicMax(fp + j, __float_as_int(v));
    }
}

// ---------------- scatter pillars -> fp16 plane + occ ----------------
__global__ void scatter_kernel(const int* __restrict__ unq, const float* __restrict__ fv,
                               __half* __restrict__ ah, float* __restrict__ occ)
{
    int idx = blockIdx.x * blockDim.x + threadIdx.x;
    if (idx >= MPIL * 8) return;
    int m = idx >> 3, k = idx & 7;
    int bb = unq[m*3], yy = unq[m*3+1], xx = unq[m*3+2];
    const float4* fp = reinterpret_cast<const float4*>(fv) + m * 16 + 2 * k;
    float4 a = fp[0], b = fp[1];
    uint4 hw;
    hw.x = pack_h2(a.x, a.y);
    hw.y = pack_h2(a.z, a.w);
    hw.z = pack_h2(b.x, b.y);
    hw.w = pack_h2(b.z, b.w);
    size_t pix = ((size_t)(bb * GS + yy) * GS + xx) * 64;
    reinterpret_cast<uint4*>(ah + pix)[k] = hw;
    if (k == 0) occ[(bb * GS + yy) * GS + xx] = 1.0f;
}

// ---------------- occupancy dilations ----------------
__global__ void occ1_kernel(const float* __restrict__ occ, float* __restrict__ occ1) {
    int idx = blockIdx.x * blockDim.x + threadIdx.x;
    if (idx >= BATCH * GS * GS) return;
    int x = idx % GS, y = (idx / GS) % GS, b = idx / (GS * GS);
    float m = 0.f;
#pragma unroll
    for (int dy = -1; dy <= 1; dy++)
#pragma unroll
        for (int dx = -1; dx <= 1; dx++) {
            int yy = y + dy, xx = x + dx;
            if (yy >= 0 && yy < GS && xx >= 0 && xx < GS)
                m = fmaxf(m, occ[(b * GS + yy) * GS + xx]);
        }
    occ1[idx] = m;
}
__global__ void occ2_kernel(const float* __restrict__ occ1, float* __restrict__ occ2) {
    int idx = blockIdx.x * blockDim.x + threadIdx.x;
    if (idx >= BATCH * GS2 * GS2) return;
    int x = idx % GS2, y = (idx / GS2) % GS2, b = idx / (GS2 * GS2);
    float m = 0.f;
#pragma unroll
    for (int dy = -1; dy <= 1; dy++)
#pragma unroll
        for (int dx = -1; dx <= 1; dx++) {
            int yy = 2 * y + dy, xx = 2 * x + dx;
            if (yy >= 0 && yy < GS && xx >= 0 && xx < GS)
                m = fmaxf(m, occ1[(b * GS + yy) * GS + xx]);
        }
    occ2[idx] = m;
}

// ---------------- HMMA conv3x3 (fp16), cp.async pipelined, ldmatrix A ----------------
template <int CIN, int COUT, int STRIDE, int TM, int BUFS, bool RESID, bool OUTF32, bool PLANES>
__global__ __launch_bounds__(256) void conv_mma(
    const __half* __restrict__ in,
    const uint2* __restrict__ wfrag,
    const float* __restrict__ gm, const float* __restrict__ bt,
    const float* __restrict__ mask, const float* __restrict__ resid,
    float* __restrict__ outf, __half* __restrict__ outh,
    int IH, int IW, int OH, int OW)
{
    constexpr int CHUNKS = CIN / 16;
    constexpr int NTTOT = COUT / 8;
    constexpr int NT = COUT / 16;
    constexpr int R = (TM - 1) * STRIDE + 3;
    constexpr int PXW = 64 * STRIDE + 2;
    constexpr int NV = R * PXW * 2;

    extern __shared__ __align__(16) char smem_raw[];
    __half* s_in = reinterpret_cast<__half*>(smem_raw);
    auto sidx = [&](int buf, int ry, int px) {
        return ((buf * R + ry) * PXW + px) * 16;
    };

    const int tid = threadIdx.x;
    const int wid = tid >> 5, lane = tid & 31;
    const int mwarp = wid >> 1, nwarp = wid & 1;
    const int g = lane >> 2, q = lane & 3;
    const int y0 = blockIdx.y * TM;
    const int xb = blockIdx.x * 64;
    const int bb = blockIdx.z;

    const int mat = lane >> 3;
    const int mrow = (mat & 1) * 8 + (lane & 7);
    const int koff = (mat >> 1) * 8;
    const int pxbase = (mwarp * 16 + mrow) * STRIDE;
    const uint32_t sb32 = smem_u32(s_in);

    float acc[TM][NT][4];
#pragma unroll
    for (int r = 0; r < TM; r++)
#pragma unroll
        for (int nt = 0; nt < NT; nt++)
#pragma unroll
            for (int j = 0; j < 4; j++) acc[r][nt][j] = 0.f;

    auto stage = [&](int ch, int buf) {
#pragma unroll 1
        for (int i = tid; i < NV; i += 256) {
            int half = i & 1;
            int r2 = i >> 1;
            int px = r2 % PXW;
            int ry = r2 / PXW;
            int iy = y0 * STRIDE + ry - 1;
            int ix = xb * STRIDE + px - 1;
            bool ok = (iy >= 0) && (iy < IH) && (ix >= 0) && (ix < IW);
            const void* src = ok
                ? (const void*)(in + ((size_t)(bb * IH + iy) * IW + ix) * CIN + ch * 16 + half * 8)
                : (const void*)in;
            cp16(smem_u32(s_in + sidx(buf, ry, px) + half * 8), src, ok);
        }
        cp_commit();
    };

    stage(0, 0);

#pragma unroll 1
    for (int ch = 0; ch < CHUNKS; ch++) {
        const int buf = (BUFS == 3) ? (ch % 3) : (ch & 1);
        if (ch + 1 < CHUNKS) {
            stage(ch + 1, (BUFS == 3) ? ((ch + 1) % 3) : ((ch + 1) & 1));
            cp_wait<1>();
        } else {
            cp_wait<0>();
        }
        __syncthreads();
#pragma unroll
        for (int ky = 0; ky < 3; ky++) {
#pragma unroll
            for (int kx = 0; kx < 3; kx++) {
                const uint2* bbase = wfrag
                    + (size_t)(((ky * 3 + kx) * CHUNKS + ch) * NTTOT + nwarp * NT) * 32;
                uint2 bh[NT];
#pragma unroll
                for (int nt = 0; nt < NT; nt++) bh[nt] = __ldg(bbase + nt * 32 + lane);
                uint32_t A[TM][4];
#pragma unroll
                for (int r = 0; r < TM; r++) {
                    const int row = r * STRIDE + ky;
                    uint32_t ad = sb32 + (uint32_t)((((buf * R + row) * PXW) + pxbase + kx) * 16 + koff) * 2;
                    ldsm_x4(A[r][0], A[r][1], A[r][2], A[r][3], ad);
                }
#pragma unroll
                for (int r = 0; r < TM; r++)
#pragma unroll
                    for (int nt = 0; nt < NT; nt++)
                        mma16816(acc[r][nt], A[r], bh[nt].x, bh[nt].y);
            }
        }
        if (BUFS == 2) __syncthreads();
    }

    // epilogue
    const int xa = xb + mwarp * 16 + g;
#pragma unroll
    for (int r = 0; r < TM; r++) {
        const int y = y0 + r;
        const size_t pa = (size_t)(bb * OH + y) * OW + xa;
        const size_t pb = pa + 8;
        const float mva = mask[pa];
        const float mvb = mask[pb];
#pragma unroll
        for (int nt = 0; nt < NT; nt++) {
            const int co = nwarp * (COUT / 2) + nt * 8 + 2 * q;
            const float g0 = __ldg(gm + co), g1 = __ldg(gm + co + 1);
            const float b0 = __ldg(bt + co), b1 = __ldg(bt + co + 1);
            float v0 = acc[r][nt][0] * g0 + b0;
            float v1 = acc[r][nt][1] * g1 + b1;
            float v2 = acc[r][nt][2] * g0 + b0;
            float v3 = acc[r][nt][3] * g1 + b1;
            if (RESID) {
                float2 ra = *reinterpret_cast<const float2*>(resid + pa * COUT + co);
                float2 rb = *reinterpret_cast<const float2*>(resid + pb * COUT + co);
                v0 = fmaxf(ra.x + v0 * mva, 0.f);
                v1 = fmaxf(ra.y + v1 * mva, 0.f);
                v2 = fmaxf(rb.x + v2 * mvb, 0.f);
                v3 = fmaxf(rb.y + v3 * mvb, 0.f);
            } else {
                v0 = fmaxf(v0, 0.f) * mva;
                v1 = fmaxf(v1, 0.f) * mva;
                v2 = fmaxf(v2, 0.f) * mvb;
                v3 = fmaxf(v3, 0.f) * mvb;
            }
            if (OUTF32) {
                *reinterpret_cast<float2*>(outf + pa * COUT + co) = make_float2(v0, v1);
                *reinterpret_cast<float2*>(outf + pb * COUT + co) = make_float2(v2, v3);
            }
            if (PLANES) {
                *reinterpret_cast<uint32_t*>(outh + pa * COUT + co) = pack_h2(v0, v1);
                *reinterpret_cast<uint32_t*>(outh + pb * COUT + co) = pack_h2(v2, v3);
            }
        }
    }
}

// ---------------- bilinear gather (fp16 feature plane) ----------------
__global__ __launch_bounds__(256) void gather_kernel(
    const float* __restrict__ feat, const int* __restrict__ unq, const int* __restrict__ inv,
    const __half* __restrict__ xh, float* __restrict__ out)
{
    int gwarp = (blockIdx.x * blockDim.x + threadIdx.x) >> 5;
    int lane = threadIdx.x & 31;
    if (gwarp >= NPTS) return;
    int i = gwarp;
    float f0 = __ldg(feat + (size_t)i * 16);
    float f1 = __ldg(feat + (size_t)i * 16 + 1);
    float px = ((f0 + 51.2f) / 0.4f) * 0.5f;
    float py = ((f1 + 51.2f) / 0.4f) * 0.5f;
    int seg = __ldg(inv + i);
    int bb = __ldg(unq + seg * 3);
    int fx = (int)floorf(px), fy = (int)floorf(py);
    int x0 = min(max(fx, 0), GS2 - 1), x1 = min(max(fx + 1, 0), GS2 - 1);
    int y0 = min(max(fy, 0), GS2 - 1), y1 = min(max(fy + 1, 0), GS2 - 1);
    float x0f = (float)x0, x1f = (float)x1, y0f = (float)y0, y1f = (float)y1;
    float wa = (x1f - px) * (y1f - py);
    float wb = (x1f - px) * (py - y0f);
    float wc = (px - x0f) * (y1f - py);
    float wd = (px - x0f) * (py - y0f);
    const uint2* A  = reinterpret_cast<const uint2*>(xh + ((size_t)(bb*GS2+y0)*GS2+x0)*C2) + lane;
    const uint2* Bp = reinterpret_cast<const uint2*>(xh + ((size_t)(bb*GS2+y1)*GS2+x0)*C2) + lane;
    const uint2* Cp = reinterpret_cast<const uint2*>(xh + ((size_t)(bb*GS2+y0)*GS2+x1)*C2) + lane;
    const uint2* D  = reinterpret_cast<const uint2*>(xh + ((size_t)(bb*GS2+y1)*GS2+x1)*C2) + lane;
    uint2 ua = __ldg(A), ub = __ldg(Bp), uc = __ldg(Cp), ud = __ldg(D);
    float2 a0 = __half22float2(*reinterpret_cast<__half2*>(&ua.x));
    float2 a1 = __half22float2(*reinterpret_cast<__half2*>(&ua.y));
    float2 b0 = __half22float2(*reinterpret_cast<__half2*>(&ub.x));
    float2 b1 = __half22float2(*reinterpret_cast<__half2*>(&ub.y));
    float2 c0 = __half22float2(*reinterpret_cast<__half2*>(&uc.x));
    float2 c1 = __half22float2(*reinterpret_cast<__half2*>(&uc.y));
    float2 d0 = __half22float2(*reinterpret_cast<__half2*>(&ud.x));
    float2 d1 = __half22float2(*reinterpret_cast<__half2*>(&ud.y));
    float4 r;
    r.x = a0.x*wa + b0.x*wb + c0.x*wc + d0.x*wd;
    r.y = a0.y*wa + b0.y*wb + c0.y*wc + d0.y*wd;
    r.z = a1.x*wa + b1.x*wb + c1.x*wc + d1.x*wd;
    r.w = a1.y*wa + b1.y*wb + c1.y*wc + d1.y*wd;
    reinterpret_cast<float4*>(out + (size_t)i * C2)[lane] = r;
}

// ---------------- launch ----------------
extern "C" void kernel_launch(void* const* d_in, const int* in_sizes, int n_in,
                              void* d_out, int out_size)
{
    const float* feat = (const float*)d_in[0];
    const int* unq = (const int*)d_in[1];
    const int* inv = (const int*)d_in[2];
    int wb = (in_sizes[3] == 1) ? 4 : 3;
    const float* W[24];
    for (int i = 0; i < 24; i++) W[i] = (const float*)d_in[wb + i];
    float* out = (float*)d_out;

    float *p_h0, *p_hmax, *p_fv, *p_x1, *p_x2, *p_occ, *p_occ1, *p_occ2;
    __half *a0, *a1, *a2, *a3, *a4, *a5, *xb2h;
    uint2* p_wf;
    cudaGetSymbolAddress((void**)&p_h0, g_h0);
    cudaGetSymbolAddress((void**)&p_hmax, g_hmax);
    cudaGetSymbolAddress((void**)&p_fv, g_fv);
    cudaGetSymbolAddress((void**)&p_x1, g_x1);
    cudaGetSymbolAddress((void**)&p_x2, g_x2);
    cudaGetSymbolAddress((void**)&p_occ, g_occ);
    cudaGetSymbolAddress((void**)&p_occ1, g_occ1);
    cudaGetSymbolAddress((void**)&p_occ2, g_occ2);
    cudaGetSymbolAddress((void**)&a0, g_a0);
    cudaGetSymbolAddress((void**)&a1, g_a1);
    cudaGetSymbolAddress((void**)&a2, g_a2);
    cudaGetSymbolAddress((void**)&a3, g_a3);
    cudaGetSymbolAddress((void**)&a4, g_a4);
    cudaGetSymbolAddress((void**)&a5, g_a5);
    cudaGetSymbolAddress((void**)&xb2h, g_xb2h);
    cudaGetSymbolAddress((void**)&p_wf, g_wfrag);

    // merged zero: a0 (fp16 plane), hmax, fv, occ
    const int N0 = BATCH*GS*GS*C1*2/16;
    const int N1 = MPIL*16*4/16;
    const int N2 = MPIL*64*4/16;
    const int N3 = BATCH*GS*GS*4/16;
    zero_all_kernel<<<(N0+N1+N2+N3 + 255)/256, 256>>>(
        (uint4*)a0, N0, (uint4*)p_hmax, N1, (uint4*)p_fv, N2, (uint4*)p_occ, N3);

    wprep_all_kernel<<<(119808 + 255)/256, 256>>>(
        W[6], W[9], W[12], W[15], W[18], W[21], p_wf);

    pfn0_kernel<<<(NPTS + 255)/256, 256>>>(feat, inv, W[0], W[1], W[2], p_h0, p_hmax);
    pfn1_kernel<<<(NPTS + 127)/128, 128>>>(inv, W[3], W[4], W[5], p_h0, p_hmax, p_fv);
    scatter_kernel<<<(MPIL*8 + 255)/256, 256>>>(unq, p_fv, a0, p_occ);
    occ1_kernel<<<(BATCH*GS*GS + 255)/256, 256>>>(p_occ, p_occ1);
    occ2_kernel<<<(BATCH*GS2*GS2 + 255)/256, 256>>>(p_occ1, p_occ2);

    // dynamic smem: BUFS * R * PXW * 16 halves * 2B
    const int S13 = 3 * 6 * 66 * 16 * 2;   // 38016 (TM=4, s1, BUFS=3)
    const int S4  = 2 * 5 * 130 * 16 * 2;  // 41600 (TM=2, s2, BUFS=2)
    const int S56 = 3 * 4 * 66 * 16 * 2;   // 25344 (TM=2, s1, BUFS=3)
    cudaFuncSetAttribute(conv_mma<64,64,1,4,3,false,true,true>,   cudaFuncAttributeMaxDynamicSharedMemorySize, S13);
    cudaFuncSetAttribute(conv_mma<64,64,1,4,3,false,false,true>,  cudaFuncAttributeMaxDynamicSharedMemorySize, S13);
    cudaFuncSetAttribute(conv_mma<64,64,1,4,3,true,false,true>,   cudaFuncAttributeMaxDynamicSharedMemorySize, S13);
    cudaFuncSetAttribute(conv_mma<64,128,2,2,2,false,true,true>,  cudaFuncAttributeMaxDynamicSharedMemorySize, S4);
    cudaFuncSetAttribute(conv_mma<128,128,1,2,3,false,false,true>,cudaFuncAttributeMaxDynamicSharedMemorySize, S56);
    cudaFuncSetAttribute(conv_mma<128,128,1,2,3,true,false,true>, cudaFuncAttributeMaxDynamicSharedMemorySize, S56);

    dim3 blk(256);
    // L1-3: 64->64 s1, TM=4, BUFS=3: grid (4, 64, 2)
    dim3 g1(GS/64, GS/4, BATCH);
    conv_mma<64,64,1,4,3,false,true,true><<<g1, blk, S13>>>(
        a0, p_wf + FOFF1, W[7], W[8], p_occ1, nullptr, p_x1, a1, GS, GS, GS, GS);
    conv_mma<64,64,1,4,3,false,false,true><<<g1, blk, S13>>>(
        a1, p_wf + FOFF2, W[10], W[11], p_occ1, nullptr, nullptr, a2, GS, GS, GS, GS);
    conv_mma<64,64,1,4,3,true,false,true><<<g1, blk, S13>>>(
        a2, p_wf + FOFF3, W[13], W[14], p_occ1, p_x1, nullptr, a3, GS, GS, GS, GS);

    // L4: 64->128 s2, TM=2, BUFS=2: grid (2, 64, 2)
    dim3 g2(GS2/64, GS2/2, BATCH);
    conv_mma<64,128,2,2,2,false,true,true><<<g2, blk, S4>>>(
        a3, p_wf + FOFF4, W[16], W[17], p_occ2, nullptr, p_x2, a4, GS, GS, GS2, GS2);
    // L5: 128->128 s1
    conv_mma<128,128,1,2,3,false,false,true><<<g2, blk, S56>>>(
        a4, p_wf + FOFF5, W[19], W[20], p_occ2, nullptr, nullptr, a5, GS2, GS2, GS2, GS2);
    // L6: 128->128 s1 + residual, emit fp16 plane for gather
    conv_mma<128,128,1,2,3,true,false,true><<<g2, blk, S56>>>(
        a5, p_wf + FOFF6, W[22], W[23], p_occ2, p_x2, nullptr, xb2h, GS2, GS2, GS2, GS2);

    gather_kernel<<<(NPTS*32 + 255)/256, 256>>>(feat, unq, inv, xb2h, out);
    (void)n_in; (void)out_size;
}

// round 14
// speedup vs baseline: 1.1007x; 1.0410x over previous
#include <cuda_runtime.h>
#include <cuda_fp16.h>
#include <cstdint>

#define NPTS 200000
#define MPIL 30000
#define BATCH 2
#define GS 256
#define GS2 128
#define C1 64
#define C2 128

// ---------------- scratch ----------------
__device__ __align__(16) __half g_a0[BATCH*GS*GS*C1];
__device__ __align__(16) __half g_a1[BATCH*GS*GS*C1];
__device__ __align__(16) __half g_a2[BATCH*GS*GS*C1];
__device__ __align__(16) __half g_a3[BATCH*GS*GS*C1];
__device__ __align__(16) __half g_a4[BATCH*GS2*GS2*C2];
__device__ __align__(16) __half g_a5[BATCH*GS2*GS2*C2];
__device__ __align__(16) float g_x1 [BATCH*GS*GS*C1];
__device__ __align__(16) float g_x2 [BATCH*GS2*GS2*C2];
__device__ __align__(16) float g_xb2[BATCH*GS2*GS2*C2];
__device__ __align__(16) float g_h0  [NPTS*16];
__device__ __align__(16) float g_hmax[MPIL*16];
__device__ __align__(16) float g_fv  [MPIL*64];
__device__ __align__(16) float g_occ [BATCH*GS*GS];
__device__ __align__(16) float g_occ1[BATCH*GS*GS];
__device__ __align__(16) float g_occ2[BATCH*GS2*GS2];

// B-fragment store: [tap][chunk][ntile] blocks of 32 uint2 (fp16 frags)
#define FOFF1 0
#define FOFF2 (FOFF1 + 9216)
#define FOFF3 (FOFF2 + 9216)
#define FOFF4 (FOFF3 + 9216)
#define FOFF5 (FOFF4 + 18432)
#define FOFF6 (FOFF5 + 36864)
#define FTOT  (FOFF6 + 36864)
__device__ __align__(16) uint2 g_wfrag[FTOT];

// ---------------- helpers ----------------
__device__ __forceinline__ uint32_t smem_u32(const void* p) {
    uint32_t a;
    asm("{ .reg .u64 t; cvta.to.shared.u64 t, %1; cvt.u32.u64 %0, t; }" : "=r"(a) : "l"(p));
    return a;
}
__device__ __forceinline__ uint32_t pack_h2(float f0, float f1) {
    uint32_t r;
    asm("cvt.rn.f16x2.f32 %0, %1, %2;" : "=r"(r) : "f"(f1), "f"(f0));
    return r;
}
__device__ __forceinline__ void mma16816(float* c, const uint32_t* a,
                                         uint32_t b0, uint32_t b1) {
    asm volatile("mma.sync.aligned.m16n8k16.row.col.f32.f16.f16.f32 "
        "{%0,%1,%2,%3}, {%4,%5,%6,%7}, {%8,%9}, {%0,%1,%2,%3};"
        : "+f"(c[0]), "+f"(c[1]), "+f"(c[2]), "+f"(c[3])
        : "r"(a[0]), "r"(a[1]), "r"(a[2]), "r"(a[3]), "r"(b0), "r"(b1));
}
__device__ __forceinline__ void ldsm_x4(uint32_t& r0, uint32_t& r1, uint32_t& r2, uint32_t& r3,
                                        uint32_t saddr) {
    asm volatile("ldmatrix.sync.aligned.m8n8.x4.shared.b16 {%0,%1,%2,%3}, [%4];"
        : "=r"(r0), "=r"(r1), "=r"(r2), "=r"(r3) : "r"(saddr));
}
__device__ __forceinline__ void cp16(uint32_t dst, const void* src, bool ok) {
    int sz = ok ? 16 : 0;
    asm volatile("cp.async.cg.shared.global [%0], [%1], 16, %2;"
        :: "r"(dst), "l"(src), "r"(sz) : "memory");
}
__device__ __forceinline__ void cp_commit() {
    asm volatile("cp.async.commit_group;" ::: "memory");
}
template <int N>
__device__ __forceinline__ void cp_wait() {
    asm volatile("cp.async.wait_group %0;" :: "n"(N) : "memory");
}

// ---------------- merged zero ----------------
__global__ void zero_all_kernel(uint4* p0, int n0, uint4* p1, int n1,
                                uint4* p2, int n2, uint4* p3, int n3) {
    int i = blockIdx.x * blockDim.x + threadIdx.x;
    uint4 z = make_uint4(0u, 0u, 0u, 0u);
    if (i < n0) p0[i] = z;
    i -= n0;
    if (i >= 0 && i < n1) p1[i] = z;
    i -= n1;
    if (i >= 0 && i < n2) p2[i] = z;
    i -= n2;
    if (i >= 0 && i < n3) p3[i] = z;
}

// ---------------- merged weight prep (all 6 layers) ----------------
__global__ void wprep_all_kernel(
    const float* w1p, const float* w2p, const float* w3p,
    const float* w4p, const float* w5p, const float* w6p,
    uint2* __restrict__ dst)
{
    int idx = blockIdx.x * blockDim.x + threadIdx.x;
    int layer, base;
    const float* w;
    int cin, cout, foff;
    if (idx < 9216)            { layer = 0; base = 0; }
    else if (idx < 18432)      { layer = 1; base = 9216; }
    else if (idx < 27648)      { layer = 2; base = 18432; }
    else if (idx < 46080)      { layer = 3; base = 27648; }
    else if (idx < 82944)      { layer = 4; base = 46080; }
    else if (idx < 119808)     { layer = 5; base = 82944; }
    else return;
    switch (layer) {
        case 0: w = w1p; cin = 64;  cout = 64;  foff = FOFF1; break;
        case 1: w = w2p; cin = 64;  cout = 64;  foff = FOFF2; break;
        case 2: w = w3p; cin = 64;  cout = 64;  foff = FOFF3; break;
        case 3: w = w4p; cin = 64;  cout = 128; foff = FOFF4; break;
        case 4: w = w5p; cin = 128; cout = 128; foff = FOFF5; break;
        default:w = w6p; cin = 128; cout = 128; foff = FOFF6; break;
    }
    int li = idx - base;
    int chunks = cin / 16;
    int nttot = cout / 8;
    int lane = li & 31;
    int t = li >> 5;
    int nt = t % nttot;
    int t2 = t / nttot;
    int ch = t2 % chunks;
    int tap = t2 / chunks;
    int n = nt * 8 + (lane >> 2);
    int k0 = (lane & 3) * 2;
    int cib = ch * 16;
    float w00 = w[((size_t)tap * cin + cib + k0)     * cout + n];
    float w01 = w[((size_t)tap * cin + cib + k0 + 1) * cout + n];
    float w10 = w[((size_t)tap * cin + cib + k0 + 8) * cout + n];
    float w11 = w[((size_t)tap * cin + cib + k0 + 9) * cout + n];
    uint2* blk = dst + foff + (size_t)((tap * chunks + ch) * nttot + nt) * 32;
    blk[lane] = make_uint2(pack_h2(w00, w01), pack_h2(w10, w11));
}

// ---------------- PFN layer 0 ----------------
__global__ __launch_bounds__(256) void pfn0_kernel(
    const float* __restrict__ feat, const int* __restrict__ inv,
    const float* __restrict__ w0, const float* __restrict__ g0, const float* __restrict__ b0,
    float* __restrict__ h0, float* __restrict__ hmax)
{
    __shared__ float sw[256];
    __shared__ float sg[16], sb[16];
    if (threadIdx.x < 256) sw[threadIdx.x] = w0[threadIdx.x];
    if (threadIdx.x < 16) { sg[threadIdx.x] = g0[threadIdx.x]; sb[threadIdx.x] = b0[threadIdx.x]; }
    __syncthreads();
    int i = blockIdx.x * 256 + threadIdx.x;
    if (i >= NPTS) return;
    float f[16];
    const float4* fp = reinterpret_cast<const float4*>(feat + (size_t)i * 16);
#pragma unroll
    for (int t = 0; t < 4; t++) {
        float4 v = fp[t];
        f[4*t]=v.x; f[4*t+1]=v.y; f[4*t+2]=v.z; f[4*t+3]=v.w;
    }
    float acc[16];
#pragma unroll
    for (int j = 0; j < 16; j++) acc[j] = 0.f;
#pragma unroll
    for (int c = 0; c < 16; c++) {
        float xv = f[c];
#pragma unroll
        for (int j = 0; j < 16; j++) acc[j] += xv * sw[c * 16 + j];
    }
    int seg = inv[i];
    float h[16];
#pragma unroll
    for (int j = 0; j < 16; j++) h[j] = fmaxf(acc[j] * sg[j] + sb[j], 0.f);
    float4* hp = reinterpret_cast<float4*>(h0 + (size_t)i * 16);
#pragma unroll
    for (int t = 0; t < 4; t++) hp[t] = make_float4(h[4*t], h[4*t+1], h[4*t+2], h[4*t+3]);
    int* hm = reinterpret_cast<int*>(hmax + (size_t)seg * 16);
#pragma unroll
    for (int j = 0; j < 16; j++)
        if (h[j] > 0.f) atomicMax(hm + j, __float_as_int(h[j]));
}

// ---------------- PFN layer 1 (R11 form) ----------------
__global__ __launch_bounds__(128) void pfn1_kernel(
    const int* __restrict__ inv,
    const float* __restrict__ w1, const float* __restrict__ g1, const float* __restrict__ b1,
    const float* __restrict__ h0, const float* __restrict__ hmax, float* __restrict__ fv)
{
    __shared__ float sw[32 * 64];
    __shared__ float sg[64], sb[64];
    for (int t = threadIdx.x; t < 2048; t += blockDim.x) sw[t] = w1[t];
    if (threadIdx.x < 64) { sg[threadIdx.x] = g1[threadIdx.x]; sb[threadIdx.x] = b1[threadIdx.x]; }
    __syncthreads();
    int i = blockIdx.x * blockDim.x + threadIdx.x;
    if (i >= NPTS) return;
    int seg = inv[i];
    float x[32];
    const float4* hp = reinterpret_cast<const float4*>(h0 + (size_t)i * 16);
    const float4* mp = reinterpret_cast<const float4*>(hmax + (size_t)seg * 16);
#pragma unroll
    for (int t = 0; t < 4; t++) {
        float4 v = hp[t];
        x[4*t]=v.x; x[4*t+1]=v.y; x[4*t+2]=v.z; x[4*t+3]=v.w;
        float4 u = mp[t];
        x[16+4*t]=u.x; x[16+4*t+1]=u.y; x[16+4*t+2]=u.z; x[16+4*t+3]=u.w;
    }
    float acc[64];
#pragma unroll
    for (int j = 0; j < 64; j++) acc[j] = 0.f;
#pragma unroll
    for (int c = 0; c < 32; c++) {
        float xv = x[c];
        const float4* wr = reinterpret_cast<const float4*>(&sw[c * 64]);
#pragma unroll
        for (int k = 0; k < 16; k++) {
            float4 w = wr[k];
            acc[4*k] += xv*w.x; acc[4*k+1] += xv*w.y;
            acc[4*k+2] += xv*w.z; acc[4*k+3] += xv*w.w;
        }
    }
    int* fp = reinterpret_cast<int*>(fv + (size_t)seg * 64);
#pragma unroll
    for (int j = 0; j < 64; j++) {
        float v = fmaxf(acc[j] * sg[j] + sb[j], 0.f);
        if (v > 0.f) atomicMax(fp + j, __float_as_int(v));
    }
}

// ---------------- scatter pillars -> fp16 plane + occ ----------------
__global__ void scatter_kernel(const int* __restrict__ unq, const float* __restrict__ fv,
                               __half* __restrict__ ah, float* __restrict__ occ)
{
    int idx = blockIdx.x * blockDim.x + threadIdx.x;
    if (idx >= MPIL * 8) return;
    int m = idx >> 3, k = idx & 7;
    int bb = unq[m*3], yy = unq[m*3+1], xx = unq[m*3+2];
    const float4* fp = reinterpret_cast<const float4*>(fv) + m * 16 + 2 * k;
    float4 a = fp[0], b = fp[1];
    uint4 hw;
    hw.x = pack_h2(a.x, a.y);
    hw.y = pack_h2(a.z, a.w);
    hw.z = pack_h2(b.x, b.y);
    hw.w = pack_h2(b.z, b.w);
    size_t pix = ((size_t)(bb * GS + yy) * GS + xx) * 64;
    reinterpret_cast<uint4*>(ah + pix)[k] = hw;
    if (k == 0) occ[(bb * GS + yy) * GS + xx] = 1.0f;
}

// ---------------- merged occupancy dilation: occ1 (3x3 s1) + occ2 (5x5 s2) ----------------
__global__ void occ12_kernel(const float* __restrict__ occ,
                             float* __restrict__ occ1, float* __restrict__ occ2) {
    int idx = blockIdx.x * blockDim.x + threadIdx.x;
    const int N1 = BATCH * GS * GS;
    if (idx < N1) {
        int x = idx % GS, y = (idx / GS) % GS, b = idx / (GS * GS);
        float m = 0.f;
#pragma unroll
        for (int dy = -1; dy <= 1; dy++)
#pragma unroll
            for (int dx = -1; dx <= 1; dx++) {
                int yy = y + dy, xx = x + dx;
                if (yy >= 0 && yy < GS && xx >= 0 && xx < GS)
                    m = fmaxf(m, occ[(b * GS + yy) * GS + xx]);
            }
        occ1[idx] = m;
        return;
    }
    idx -= N1;
    if (idx >= BATCH * GS2 * GS2) return;
    int x = idx % GS2, y = (idx / GS2) % GS2, b = idx / (GS2 * GS2);
    float m = 0.f;
#pragma unroll
    for (int dy = -2; dy <= 2; dy++)
#pragma unroll
        for (int dx = -2; dx <= 2; dx++) {
            int yy = 2 * y + dy, xx = 2 * x + dx;
            if (yy >= 0 && yy < GS && xx >= 0 && xx < GS)
                m = fmaxf(m, occ[(b * GS + yy) * GS + xx]);
        }
    occ2[idx] = m;
}

// ---------------- HMMA conv3x3 (fp16), cp.async pipelined, ldmatrix A ----------------
template <int CIN, int COUT, int STRIDE, int TM, int BUFS, bool RESID, bool OUTF32, bool PLANES>
__global__ __launch_bounds__(256) void conv_mma(
    const __half* __restrict__ in,
    const uint2* __restrict__ wfrag,
    const float* __restrict__ gm, const float* __restrict__ bt,
    const float* __restrict__ mask, const float* __restrict__ resid,
    float* __restrict__ outf, __half* __restrict__ outh,
    int IH, int IW, int OH, int OW)
{
    constexpr int CHUNKS = CIN / 16;
    constexpr int NTTOT = COUT / 8;
    constexpr int NT = COUT / 16;
    constexpr int R = (TM - 1) * STRIDE + 3;
    constexpr int PXW = 64 * STRIDE + 2;
    constexpr int NV = R * PXW * 2;

    extern __shared__ __align__(16) char smem_raw[];
    __half* s_in = reinterpret_cast<__half*>(smem_raw);
    auto sidx = [&](int buf, int ry, int px) {
        return ((buf * R + ry) * PXW + px) * 16;
    };

    const int tid = threadIdx.x;
    const int wid = tid >> 5, lane = tid & 31;
    const int mwarp = wid >> 1, nwarp = wid & 1;
    const int g = lane >> 2, q = lane & 3;
    const int y0 = blockIdx.y * TM;
    const int xb = blockIdx.x * 64;
    const int bb = blockIdx.z;

    const int mat = lane >> 3;
    const int mrow = (mat & 1) * 8 + (lane & 7);
    const int koff = (mat >> 1) * 8;
    const int pxbase = (mwarp * 16 + mrow) * STRIDE;
    const uint32_t sb32 = smem_u32(s_in);

    float acc[TM][NT][4];
#pragma unroll
    for (int r = 0; r < TM; r++)
#pragma unroll
        for (int nt = 0; nt < NT; nt++)
#pragma unroll
            for (int j = 0; j < 4; j++) acc[r][nt][j] = 0.f;

    auto stage = [&](int ch, int buf) {
#pragma unroll 1
        for (int i = tid; i < NV; i += 256) {
            int half = i & 1;
            int r2 = i >> 1;
            int px = r2 % PXW;
            int ry = r2 / PXW;
            int iy = y0 * STRIDE + ry - 1;
            int ix = xb * STRIDE + px - 1;
            bool ok = (iy >= 0) && (iy < IH) && (ix >= 0) && (ix < IW);
            const void* src = ok
                ? (const void*)(in + ((size_t)(bb * IH + iy) * IW + ix) * CIN + ch * 16 + half * 8)
                : (const void*)in;
            cp16(smem_u32(s_in + sidx(buf, ry, px) + half * 8), src, ok);
        }
        cp_commit();
    };

    stage(0, 0);

#pragma unroll 1
    for (int ch = 0; ch < CHUNKS; ch++) {
        const int buf = (BUFS == 3) ? (ch % 3) : (ch & 1);
        if (ch + 1 < CHUNKS) {
            stage(ch + 1, (BUFS == 3) ? ((ch + 1) % 3) : ((ch + 1) & 1));
            cp_wait<1>();
        } else {
            cp_wait<0>();
        }
        __syncthreads();
#pragma unroll
        for (int ky = 0; ky < 3; ky++) {
#pragma unroll
            for (int kx = 0; kx < 3; kx++) {
                const uint2* bbase = wfrag
                    + (size_t)(((ky * 3 + kx) * CHUNKS + ch) * NTTOT + nwarp * NT) * 32;
                uint2 bh[NT];
#pragma unroll
                for (int nt = 0; nt < NT; nt++) bh[nt] = __ldg(bbase + nt * 32 + lane);
                uint32_t A[TM][4];
#pragma unroll
                for (int r = 0; r < TM; r++) {
                    const int row = r * STRIDE + ky;
                    uint32_t ad = sb32 + (uint32_t)((((buf * R + row) * PXW) + pxbase + kx) * 16 + koff) * 2;
                    ldsm_x4(A[r][0], A[r][1], A[r][2], A[r][3], ad);
                }
#pragma unroll
                for (int r = 0; r < TM; r++)
#pragma unroll
                    for (int nt = 0; nt < NT; nt++)
                        mma16816(acc[r][nt], A[r], bh[nt].x, bh[nt].y);
            }
        }
        if (BUFS == 2) __syncthreads();
    }

    // epilogue
    const int xa = xb + mwarp * 16 + g;
#pragma unroll
    for (int r = 0; r < TM; r++) {
        const int y = y0 + r;
        const size_t pa = (size_t)(bb * OH + y) * OW + xa;
        const size_t pb = pa + 8;
        const float mva = mask[pa];
        const float mvb = mask[pb];
#pragma unroll
        for (int nt = 0; nt < NT; nt++) {
            const int co = nwarp * (COUT / 2) + nt * 8 + 2 * q;
            const float g0 = __ldg(gm + co), g1 = __ldg(gm + co + 1);
            const float b0 = __ldg(bt + co), b1 = __ldg(bt + co + 1);
            float v0 = acc[r][nt][0] * g0 + b0;
            float v1 = acc[r][nt][1] * g1 + b1;
            float v2 = acc[r][nt][2] * g0 + b0;
            float v3 = acc[r][nt][3] * g1 + b1;
            if (RESID) {
                float2 ra = *reinterpret_cast<const float2*>(resid + pa * COUT + co);
                float2 rb = *reinterpret_cast<const float2*>(resid + pb * COUT + co);
                v0 = fmaxf(ra.x + v0 * mva, 0.f);
                v1 = fmaxf(ra.y + v1 * mva, 0.f);
                v2 = fmaxf(rb.x + v2 * mvb, 0.f);
                v3 = fmaxf(rb.y + v3 * mvb, 0.f);
            } else {
                v0 = fmaxf(v0, 0.f) * mva;
                v1 = fmaxf(v1, 0.f) * mva;
                v2 = fmaxf(v2, 0.f) * mvb;
                v3 = fmaxf(v3, 0.f) * mvb;
            }
            if (OUTF32) {
                *reinterpret_cast<float2*>(outf + pa * COUT + co) = make_float2(v0, v1);
                *reinterpret_cast<float2*>(outf + pb * COUT + co) = make_float2(v2, v3);
            }
            if (PLANES) {
                *reinterpret_cast<uint32_t*>(outh + pa * COUT + co) = pack_h2(v0, v1);
                *reinterpret_cast<uint32_t*>(outh + pb * COUT + co) = pack_h2(v2, v3);
            }
        }
    }
}

// ---------------- bilinear gather (fp32, R11 form) ----------------
__global__ __launch_bounds__(256) void gather_kernel(
    const float* __restrict__ feat, const int* __restrict__ unq, const int* __restrict__ inv,
    const float* __restrict__ xb2, float* __restrict__ out)
{
    int gwarp = (blockIdx.x * blockDim.x + threadIdx.x) >> 5;
    int lane = threadIdx.x & 31;
    if (gwarp >= NPTS) return;
    int i = gwarp;
    float f0 = __ldg(feat + (size_t)i * 16);
    float f1 = __ldg(feat + (size_t)i * 16 + 1);
    float px = ((f0 + 51.2f) / 0.4f) * 0.5f;
    float py = ((f1 + 51.2f) / 0.4f) * 0.5f;
    int seg = __ldg(inv + i);
    int bb = __ldg(unq + seg * 3);
    int fx = (int)floorf(px), fy = (int)floorf(py);
    int x0 = min(max(fx, 0), GS2 - 1), x1 = min(max(fx + 1, 0), GS2 - 1);
    int y0 = min(max(fy, 0), GS2 - 1), y1 = min(max(fy + 1, 0), GS2 - 1);
    float x0f = (float)x0, x1f = (float)x1, y0f = (float)y0, y1f = (float)y1;
    float wa = (x1f - px) * (y1f - py);
    float wb = (x1f - px) * (py - y0f);
    float wc = (px - x0f) * (y1f - py);
    float wd = (px - x0f) * (py - y0f);
    const float4* A  = reinterpret_cast<const float4*>(xb2 + ((size_t)(bb*GS2+y0)*GS2+x0)*C2) + lane;
    const float4* Bp = reinterpret_cast<const float4*>(xb2 + ((size_t)(bb*GS2+y1)*GS2+x0)*C2) + lane;
    const float4* Cp = reinterpret_cast<const float4*>(xb2 + ((size_t)(bb*GS2+y0)*GS2+x1)*C2) + lane;
    const float4* D  = reinterpret_cast<const float4*>(xb2 + ((size_t)(bb*GS2+y1)*GS2+x1)*C2) + lane;
    float4 a = __ldg(A), b = __ldg(Bp), c = __ldg(Cp), d = __ldg(D);
    float4 r;
    r.x = a.x*wa + b.x*wb + c.x*wc + d.x*wd;
    r.y = a.y*wa + b.y*wb + c.y*wc + d.y*wd;
    r.z = a.z*wa + b.z*wb + c.z*wc + d.z*wd;
    r.w = a.w*wa + b.w*wb + c.w*wc + d.w*wd;
    reinterpret_cast<float4*>(out + (size_t)i * C2)[lane] = r;
}

// ---------------- launch ----------------
extern "C" void kernel_launch(void* const* d_in, const int* in_sizes, int n_in,
                              void* d_out, int out_size)
{
    const float* feat = (const float*)d_in[0];
    const int* unq = (const int*)d_in[1];
    const int* inv = (const int*)d_in[2];
    int wb = (in_sizes[3] == 1) ? 4 : 3;
    const float* W[24];
    for (int i = 0; i < 24; i++) W[i] = (const float*)d_in[wb + i];
    float* out = (float*)d_out;

    float *p_h0, *p_hmax, *p_fv, *p_x1, *p_x2, *p_xb2, *p_occ, *p_occ1, *p_occ2;
    __half *a0, *a1, *a2, *a3, *a4, *a5;
    uint2* p_wf;
    cudaGetSymbolAddress((void**)&p_h0, g_h0);
    cudaGetSymbolAddress((void**)&p_hmax, g_hmax);
    cudaGetSymbolAddress((void**)&p_fv, g_fv);
    cudaGetSymbolAddress((void**)&p_x1, g_x1);
    cudaGetSymbolAddress((void**)&p_x2, g_x2);
    cudaGetSymbolAddress((void**)&p_xb2, g_xb2);
    cudaGetSymbolAddress((void**)&p_occ, g_occ);
    cudaGetSymbolAddress((void**)&p_occ1, g_occ1);
    cudaGetSymbolAddress((void**)&p_occ2, g_occ2);
    cudaGetSymbolAddress((void**)&a0, g_a0);
    cudaGetSymbolAddress((void**)&a1, g_a1);
    cudaGetSymbolAddress((void**)&a2, g_a2);
    cudaGetSymbolAddress((void**)&a3, g_a3);
    cudaGetSymbolAddress((void**)&a4, g_a4);
    cudaGetSymbolAddress((void**)&a5, g_a5);
    cudaGetSymbolAddress((void**)&p_wf, g_wfrag);

    // merged zero: a0 (fp16 plane), hmax, fv, occ
    const int N0 = BATCH*GS*GS*C1*2/16;
    const int N1 = MPIL*16*4/16;
    const int N2 = MPIL*64*4/16;
    const int N3 = BATCH*GS*GS*4/16;
    zero_all_kernel<<<(N0+N1+N2+N3 + 255)/256, 256>>>(
        (uint4*)a0, N0, (uint4*)p_hmax, N1, (uint4*)p_fv, N2, (uint4*)p_occ, N3);

    wprep_all_kernel<<<(119808 + 255)/256, 256>>>(
        W[6], W[9], W[12], W[15], W[18], W[21], p_wf);

    pfn0_kernel<<<(NPTS + 255)/256, 256>>>(feat, inv, W[0], W[1], W[2], p_h0, p_hmax);
    pfn1_kernel<<<(NPTS + 127)/128, 128>>>(inv, W[3], W[4], W[5], p_h0, p_hmax, p_fv);
    scatter_kernel<<<(MPIL*8 + 255)/256, 256>>>(unq, p_fv, a0, p_occ);
    occ12_kernel<<<(BATCH*GS*GS + BATCH*GS2*GS2 + 255)/256, 256>>>(p_occ, p_occ1, p_occ2);

    // dynamic smem: BUFS * R * PXW * 16 halves * 2B
    const int S13 = 3 * 6 * 66 * 16 * 2;   // 38016 (TM=4, s1, BUFS=3)
    const int S4  = 3 * 5 * 130 * 16 * 2;  // 62400 (TM=2, s2, BUFS=3)
    const int S56 = 3 * 4 * 66 * 16 * 2;   // 25344 (TM=2, s1, BUFS=3)
    cudaFuncSetAttribute(conv_mma<64,64,1,4,3,false,true,true>,   cudaFuncAttributeMaxDynamicSharedMemorySize, S13);
    cudaFuncSetAttribute(conv_mma<64,64,1,4,3,false,false,true>,  cudaFuncAttributeMaxDynamicSharedMemorySize, S13);
    cudaFuncSetAttribute(conv_mma<64,64,1,4,3,true,false,true>,   cudaFuncAttributeMaxDynamicSharedMemorySize, S13);
    cudaFuncSetAttribute(conv_mma<64,128,2,2,3,false,true,true>,  cudaFuncAttributeMaxDynamicSharedMemorySize, S4);
    cudaFuncSetAttribute(conv_mma<128,128,1,2,3,false,false,true>,cudaFuncAttributeMaxDynamicSharedMemorySize, S56);
    cudaFuncSetAttribute(conv_mma<128,128,1,2,3,true,true,false>, cudaFuncAttributeMaxDynamicSharedMemorySize, S56);

    dim3 blk(256);
    // L1-3: 64->64 s1, TM=4, BUFS=3: grid (4, 64, 2)
    dim3 g1(GS/64, GS/4, BATCH);
    conv_mma<64,64,1,4,3,false,true,true><<<g1, blk, S13>>>(
        a0, p_wf + FOFF1, W[7], W[8], p_occ1, nullptr, p_x1, a1, GS, GS, GS, GS);
    conv_mma<64,64,1,4,3,false,false,true><<<g1, blk, S13>>>(
        a1, p_wf + FOFF2, W[10], W[11], p_occ1, nullptr, nullptr, a2, GS, GS, GS, GS);
    conv_mma<64,64,1,4,3,true,false,true><<<g1, blk, S13>>>(
        a2, p_wf + FOFF3, W[13], W[14], p_occ1, p_x1, nullptr, a3, GS, GS, GS, GS);

    // L4: 64->128 s2, TM=2, BUFS=3 single-sync: grid (2, 64, 2)
    dim3 g2(GS2/64, GS2/2, BATCH);
    conv_mma<64,128,2,2,3,false,true,true><<<g2, blk, S4>>>(
        a3, p_wf + FOFF4, W[16], W[17], p_occ2, nullptr, p_x2, a4, GS, GS, GS2, GS2);
    // L5: 128->128 s1
    conv_mma<128,128,1,2,3,false,false,true><<<g2, blk, S56>>>(
        a4, p_wf + FOFF5, W[19], W[20], p_occ2, nullptr, nullptr, a5, GS2, GS2, GS2, GS2);
    // L6: 128->128 s1 + residual, fp32 output for gather (R11 form)
    conv_mma<128,128,1,2,3,true,true,false><<<g2, blk, S56>>>(
        a5, p_wf + FOFF6, W[22], W[23], p_occ2, p_x2, p_xb2, nullptr, GS2, GS2, GS2, GS2);

    gather_kernel<<<(NPTS*32 + 255)/256, 256>>>(feat, unq, inv, p_xb2, out);
    (void)n_in; (void)out_size;
}

// round 15
// speedup vs baseline: 1.1028x; 1.0019x over previous
#include <cuda_runtime.h>
#include <cuda_fp16.h>
#include <cstdint>

#define NPTS 200000
#define MPIL 30000
#define BATCH 2
#define GS 256
#define GS2 128
#define C1 64
#define C2 128

// ---------------- scratch ----------------
__device__ __align__(16) __half g_a0[BATCH*GS*GS*C1];
__device__ __align__(16) __half g_a1[BATCH*GS*GS*C1];
__device__ __align__(16) __half g_a2[BATCH*GS*GS*C1];
__device__ __align__(16) __half g_a3[BATCH*GS*GS*C1];
__device__ __align__(16) __half g_a4[BATCH*GS2*GS2*C2];
__device__ __align__(16) __half g_a5[BATCH*GS2*GS2*C2];
__device__ __align__(16) float g_x1 [BATCH*GS*GS*C1];
__device__ __align__(16) float g_x2 [BATCH*GS2*GS2*C2];
__device__ __align__(16) float g_xb2[BATCH*GS2*GS2*C2];
__device__ __align__(16) float g_h0  [NPTS*16];
__device__ __align__(16) float g_hmax[MPIL*16];
__device__ __align__(16) float g_fv  [MPIL*64];
__device__ __align__(16) float g_occ [BATCH*GS*GS];
__device__ __align__(16) float g_occ1[BATCH*GS*GS];
__device__ __align__(16) float g_occ2[BATCH*GS2*GS2];

// B-fragment store: [tap][chunk][ntile] blocks of 32 uint2 (fp16 frags)
#define FOFF1 0
#define FOFF2 (FOFF1 + 9216)
#define FOFF3 (FOFF2 + 9216)
#define FOFF4 (FOFF3 + 9216)
#define FOFF5 (FOFF4 + 18432)
#define FOFF6 (FOFF5 + 36864)
#define FTOT  (FOFF6 + 36864)
__device__ __align__(16) uint2 g_wfrag[FTOT];

// ---------------- helpers ----------------
__device__ __forceinline__ uint32_t smem_u32(const void* p) {
    uint32_t a;
    asm("{ .reg .u64 t; cvta.to.shared.u64 t, %1; cvt.u32.u64 %0, t; }" : "=r"(a) : "l"(p));
    return a;
}
__device__ __forceinline__ uint32_t pack_h2(float f0, float f1) {
    uint32_t r;
    asm("cvt.rn.f16x2.f32 %0, %1, %2;" : "=r"(r) : "f"(f1), "f"(f0));
    return r;
}
__device__ __forceinline__ unsigned long long bcast2(float v) {
    unsigned long long r;
    asm("mov.b64 %0, {%1, %1};" : "=l"(r) : "f"(v));
    return r;
}
__device__ __forceinline__ unsigned long long packf2(float lo, float hi) {
    unsigned long long r;
    asm("mov.b64 %0, {%1, %2};" : "=l"(r) : "f"(lo), "f"(hi));
    return r;
}
__device__ __forceinline__ void ffma2(unsigned long long& acc, unsigned long long a,
                                      unsigned long long b) {
    asm("fma.rn.f32x2 %0, %1, %2, %0;" : "+l"(acc) : "l"(a), "l"(b));
}
__device__ __forceinline__ void unpackf2(unsigned long long v, float& lo, float& hi) {
    asm("mov.b64 {%0, %1}, %2;" : "=f"(lo), "=f"(hi) : "l"(v));
}
__device__ __forceinline__ void mma16816(float* c, const uint32_t* a,
                                         uint32_t b0, uint32_t b1) {
    asm volatile("mma.sync.aligned.m16n8k16.row.col.f32.f16.f16.f32 "
        "{%0,%1,%2,%3}, {%4,%5,%6,%7}, {%8,%9}, {%0,%1,%2,%3};"
        : "+f"(c[0]), "+f"(c[1]), "+f"(c[2]), "+f"(c[3])
        : "r"(a[0]), "r"(a[1]), "r"(a[2]), "r"(a[3]), "r"(b0), "r"(b1));
}
__device__ __forceinline__ void ldsm_x4(uint32_t& r0, uint32_t& r1, uint32_t& r2, uint32_t& r3,
                                        uint32_t saddr) {
    asm volatile("ldmatrix.sync.aligned.m8n8.x4.shared.b16 {%0,%1,%2,%3}, [%4];"
        : "=r"(r0), "=r"(r1), "=r"(r2), "=r"(r3) : "r"(saddr));
}
__device__ __forceinline__ void cp16(uint32_t dst, const void* src, bool ok) {
    int sz = ok ? 16 : 0;
    asm volatile("cp.async.cg.shared.global [%0], [%1], 16, %2;"
        :: "r"(dst), "l"(src), "r"(sz) : "memory");
}
__device__ __forceinline__ void cp_commit() {
    asm volatile("cp.async.commit_group;" ::: "memory");
}
template <int N>
__device__ __forceinline__ void cp_wait() {
    asm volatile("cp.async.wait_group %0;" :: "n"(N) : "memory");
}

// ---------------- merged zero ----------------
__global__ void zero_all_kernel(uint4* p0, int n0, uint4* p1, int n1,
                                uint4* p2, int n2, uint4* p3, int n3) {
    int i = blockIdx.x * blockDim.x + threadIdx.x;
    uint4 z = make_uint4(0u, 0u, 0u, 0u);
    if (i < n0) p0[i] = z;
    i -= n0;
    if (i >= 0 && i < n1) p1[i] = z;
    i -= n1;
    if (i >= 0 && i < n2) p2[i] = z;
    i -= n2;
    if (i >= 0 && i < n3) p3[i] = z;
}

// ---------------- merged weight prep (all 6 layers) ----------------
__global__ void wprep_all_kernel(
    const float* w1p, const float* w2p, const float* w3p,
    const float* w4p, const float* w5p, const float* w6p,
    uint2* __restrict__ dst)
{
    int idx = blockIdx.x * blockDim.x + threadIdx.x;
    int layer, base;
    const float* w;
    int cin, cout, foff;
    if (idx < 9216)            { layer = 0; base = 0; }
    else if (idx < 18432)      { layer = 1; base = 9216; }
    else if (idx < 27648)      { layer = 2; base = 18432; }
    else if (idx < 46080)      { layer = 3; base = 27648; }
    else if (idx < 82944)      { layer = 4; base = 46080; }
    else if (idx < 119808)     { layer = 5; base = 82944; }
    else return;
    switch (layer) {
        case 0: w = w1p; cin = 64;  cout = 64;  foff = FOFF1; break;
        case 1: w = w2p; cin = 64;  cout = 64;  foff = FOFF2; break;
        case 2: w = w3p; cin = 64;  cout = 64;  foff = FOFF3; break;
        case 3: w = w4p; cin = 64;  cout = 128; foff = FOFF4; break;
        case 4: w = w5p; cin = 128; cout = 128; foff = FOFF5; break;
        default:w = w6p; cin = 128; cout = 128; foff = FOFF6; break;
    }
    int li = idx - base;
    int chunks = cin / 16;
    int nttot = cout / 8;
    int lane = li & 31;
    int t = li >> 5;
    int nt = t % nttot;
    int t2 = t / nttot;
    int ch = t2 % chunks;
    int tap = t2 / chunks;
    int n = nt * 8 + (lane >> 2);
    int k0 = (lane & 3) * 2;
    int cib = ch * 16;
    float w00 = w[((size_t)tap * cin + cib + k0)     * cout + n];
    float w01 = w[((size_t)tap * cin + cib + k0 + 1) * cout + n];
    float w10 = w[((size_t)tap * cin + cib + k0 + 8) * cout + n];
    float w11 = w[((size_t)tap * cin + cib + k0 + 9) * cout + n];
    uint2* blk = dst + foff + (size_t)((tap * chunks + ch) * nttot + nt) * 32;
    blk[lane] = make_uint2(pack_h2(w00, w01), pack_h2(w10, w11));
}

// ---------------- PFN layer 0 (packed f32x2 FFMA) ----------------
__global__ __launch_bounds__(256) void pfn0_kernel(
    const float* __restrict__ feat, const int* __restrict__ inv,
    const float* __restrict__ w0, const float* __restrict__ g0, const float* __restrict__ b0,
    float* __restrict__ h0, float* __restrict__ hmax)
{
    __shared__ float sw[256];
    __shared__ float sg[16], sb[16];
    if (threadIdx.x < 256) sw[threadIdx.x] = w0[threadIdx.x];
    if (threadIdx.x < 16) { sg[threadIdx.x] = g0[threadIdx.x]; sb[threadIdx.x] = b0[threadIdx.x]; }
    __syncthreads();
    int i = blockIdx.x * 256 + threadIdx.x;
    if (i >= NPTS) return;
    float f[16];
    const float4* fp = reinterpret_cast<const float4*>(feat + (size_t)i * 16);
#pragma unroll
    for (int t = 0; t < 4; t++) {
        float4 v = fp[t];
        f[4*t]=v.x; f[4*t+1]=v.y; f[4*t+2]=v.z; f[4*t+3]=v.w;
    }
    unsigned long long acc[8];
#pragma unroll
    for (int j = 0; j < 8; j++) acc[j] = 0ull;
#pragma unroll
    for (int c = 0; c < 16; c++) {
        unsigned long long xv = bcast2(f[c]);
        const float4* wr = reinterpret_cast<const float4*>(&sw[c * 16]);
#pragma unroll
        for (int k = 0; k < 4; k++) {
            float4 w = wr[k];
            ffma2(acc[2*k],     xv, packf2(w.x, w.y));
            ffma2(acc[2*k + 1], xv, packf2(w.z, w.w));
        }
    }
    int seg = inv[i];
    float h[16];
#pragma unroll
    for (int j = 0; j < 8; j++) {
        float lo, hi;
        unpackf2(acc[j], lo, hi);
        h[2*j]   = fmaxf(lo * sg[2*j]   + sb[2*j],   0.f);
        h[2*j+1] = fmaxf(hi * sg[2*j+1] + sb[2*j+1], 0.f);
    }
    float4* hp = reinterpret_cast<float4*>(h0 + (size_t)i * 16);
#pragma unroll
    for (int t = 0; t < 4; t++) hp[t] = make_float4(h[4*t], h[4*t+1], h[4*t+2], h[4*t+3]);
    int* hm = reinterpret_cast<int*>(hmax + (size_t)seg * 16);
#pragma unroll
    for (int j = 0; j < 16; j++)
        if (h[j] > 0.f) atomicMax(hm + j, __float_as_int(h[j]));
}

// ---------------- PFN layer 1 (packed f32x2 FFMA) ----------------
__global__ __launch_bounds__(128) void pfn1_kernel(
    const int* __restrict__ inv,
    const float* __restrict__ w1, const float* __restrict__ g1, const float* __restrict__ b1,
    const float* __restrict__ h0, const float* __restrict__ hmax, float* __restrict__ fv)
{
    __shared__ float sw[32 * 64];
    __shared__ float sg[64], sb[64];
    for (int t = threadIdx.x; t < 2048; t += blockDim.x) sw[t] = w1[t];
    if (threadIdx.x < 64) { sg[threadIdx.x] = g1[threadIdx.x]; sb[threadIdx.x] = b1[threadIdx.x]; }
    __syncthreads();
    int i = blockIdx.x * blockDim.x + threadIdx.x;
    if (i >= NPTS) return;
    int seg = inv[i];
    float x[32];
    const float4* hp = reinterpret_cast<const float4*>(h0 + (size_t)i * 16);
    const float4* mp = reinterpret_cast<const float4*>(hmax + (size_t)seg * 16);
#pragma unroll
    for (int t = 0; t < 4; t++) {
        float4 v = hp[t];
        x[4*t]=v.x; x[4*t+1]=v.y; x[4*t+2]=v.z; x[4*t+3]=v.w;
        float4 u = mp[t];
        x[16+4*t]=u.x; x[16+4*t+1]=u.y; x[16+4*t+2]=u.z; x[16+4*t+3]=u.w;
    }
    unsigned long long acc[32];
#pragma unroll
    for (int j = 0; j < 32; j++) acc[j] = 0ull;
#pragma unroll
    for (int c = 0; c < 32; c++) {
        unsigned long long xv = bcast2(x[c]);
        const float4* wr = reinterpret_cast<const float4*>(&sw[c * 64]);
#pragma unroll
        for (int k = 0; k < 16; k++) {
            float4 w = wr[k];
            ffma2(acc[2*k],     xv, packf2(w.x, w.y));
            ffma2(acc[2*k + 1], xv, packf2(w.z, w.w));
        }
    }
    int* fp = reinterpret_cast<int*>(fv + (size_t)seg * 64);
#pragma unroll
    for (int j = 0; j < 32; j++) {
        float lo, hi;
        unpackf2(acc[j], lo, hi);
        float v0 = fmaxf(lo * sg[2*j]   + sb[2*j],   0.f);
        float v1 = fmaxf(hi * sg[2*j+1] + sb[2*j+1], 0.f);
        if (v0 > 0.f) atomicMax(fp + 2*j,     __float_as_int(v0));
        if (v1 > 0.f) atomicMax(fp + 2*j + 1, __float_as_int(v1));
    }
}

// ---------------- scatter pillars -> fp16 plane + occ ----------------
__global__ void scatter_kernel(const int* __restrict__ unq, const float* __restrict__ fv,
                               __half* __restrict__ ah, float* __restrict__ occ)
{
    int idx = blockIdx.x * blockDim.x + threadIdx.x;
    if (idx >= MPIL * 8) return;
    int m = idx >> 3, k = idx & 7;
    int bb = unq[m*3], yy = unq[m*3+1], xx = unq[m*3+2];
    const float4* fp = reinterpret_cast<const float4*>(fv) + m * 16 + 2 * k;
    float4 a = fp[0], b = fp[1];
    uint4 hw;
    hw.x = pack_h2(a.x, a.y);
    hw.y = pack_h2(a.z, a.w);
    hw.z = pack_h2(b.x, b.y);
    hw.w = pack_h2(b.z, b.w);
    size_t pix = ((size_t)(bb * GS + yy) * GS + xx) * 64;
    reinterpret_cast<uint4*>(ah + pix)[k] = hw;
    if (k == 0) occ[(bb * GS + yy) * GS + xx] = 1.0f;
}

// ---------------- merged occupancy dilation ----------------
__global__ void occ12_kernel(const float* __restrict__ occ,
                             float* __restrict__ occ1, float* __restrict__ occ2) {
    int idx = blockIdx.x * blockDim.x + threadIdx.x;
    const int N1 = BATCH * GS * GS;
    if (idx < N1) {
        int x = idx % GS, y = (idx / GS) % GS, b = idx / (GS * GS);
        float m = 0.f;
#pragma unroll
        for (int dy = -1; dy <= 1; dy++)
#pragma unroll
            for (int dx = -1; dx <= 1; dx++) {
                int yy = y + dy, xx = x + dx;
                if (yy >= 0 && yy < GS && xx >= 0 && xx < GS)
                    m = fmaxf(m, occ[(b * GS + yy) * GS + xx]);
            }
        occ1[idx] = m;
        return;
    }
    idx -= N1;
    if (idx >= BATCH * GS2 * GS2) return;
    int x = idx % GS2, y = (idx / GS2) % GS2, b = idx / (GS2 * GS2);
    float m = 0.f;
#pragma unroll
    for (int dy = -2; dy <= 2; dy++)
#pragma unroll
        for (int dx = -2; dx <= 2; dx++) {
            int yy = 2 * y + dy, xx = 2 * x + dx;
            if (yy >= 0 && yy < GS && xx >= 0 && xx < GS)
                m = fmaxf(m, occ[(b * GS + yy) * GS + xx]);
        }
    occ2[idx] = m;
}

// ---------------- HMMA conv3x3 (fp16), cp.async pipelined, ldmatrix A ----------------
template <int CIN, int COUT, int STRIDE, int TM, int BUFS, bool RESID, bool OUTF32, bool PLANES>
__global__ __launch_bounds__(256) void conv_mma(
    const __half* __restrict__ in,
    const uint2* __restrict__ wfrag,
    const float* __restrict__ gm, const float* __restrict__ bt,
    const float* __restrict__ mask, const float* __restrict__ resid,
    float* __restrict__ outf, __half* __restrict__ outh,
    int IH, int IW, int OH, int OW)
{
    constexpr int CHUNKS = CIN / 16;
    constexpr int NTTOT = COUT / 8;
    constexpr int NT = COUT / 16;
    constexpr int R = (TM - 1) * STRIDE + 3;
    constexpr int PXW = 64 * STRIDE + 2;
    constexpr int NV = R * PXW * 2;

    extern __shared__ __align__(16) char smem_raw[];
    __half* s_in = reinterpret_cast<__half*>(smem_raw);
    auto sidx = [&](int buf, int ry, int px) {
        return ((buf * R + ry) * PXW + px) * 16;
    };

    const int tid = threadIdx.x;
    const int wid = tid >> 5, lane = tid & 31;
    const int mwarp = wid >> 1, nwarp = wid & 1;
    const int g = lane >> 2, q = lane & 3;
    const int y0 = blockIdx.y * TM;
    const int xb = blockIdx.x * 64;
    const int bb = blockIdx.z;

    const int mat = lane >> 3;
    const int mrow = (mat & 1) * 8 + (lane & 7);
    const int koff = (mat >> 1) * 8;
    const int pxbase = (mwarp * 16 + mrow) * STRIDE;
    const uint32_t sb32 = smem_u32(s_in);

    float acc[TM][NT][4];
#pragma unroll
    for (int r = 0; r < TM; r++)
#pragma unroll
        for (int nt = 0; nt < NT; nt++)
#pragma unroll
            for (int j = 0; j < 4; j++) acc[r][nt][j] = 0.f;

    auto stage = [&](int ch, int buf) {
#pragma unroll 1
        for (int i = tid; i < NV; i += 256) {
            int half = i & 1;
            int r2 = i >> 1;
            int px = r2 % PXW;
            int ry = r2 / PXW;
            int iy = y0 * STRIDE + ry - 1;
            int ix = xb * STRIDE + px - 1;
            bool ok = (iy >= 0) && (iy < IH) && (ix >= 0) && (ix < IW);
            const void* src = ok
                ? (const void*)(in + ((size_t)(bb * IH + iy) * IW + ix) * CIN + ch * 16 + half * 8)
                : (const void*)in;
            cp16(smem_u32(s_in + sidx(buf, ry, px) + half * 8), src, ok);
        }
        cp_commit();
    };

    stage(0, 0);

#pragma unroll 1
    for (int ch = 0; ch < CHUNKS; ch++) {
        const int buf = (BUFS == 3) ? (ch % 3) : (ch & 1);
        if (ch + 1 < CHUNKS) {
            stage(ch + 1, (BUFS == 3) ? ((ch + 1) % 3) : ((ch + 1) & 1));
            cp_wait<1>();
        } else {
            cp_wait<0>();
        }
        __syncthreads();
#pragma unroll
        for (int ky = 0; ky < 3; ky++) {
#pragma unroll
            for (int kx = 0; kx < 3; kx++) {
                const uint2* bbase = wfrag
                    + (size_t)(((ky * 3 + kx) * CHUNKS + ch) * NTTOT + nwarp * NT) * 32;
                uint2 bh[NT];
#pragma unroll
                for (int nt = 0; nt < NT; nt++) bh[nt] = __ldg(bbase + nt * 32 + lane);
                uint32_t A[TM][4];
#pragma unroll
                for (int r = 0; r < TM; r++) {
                    const int row = r * STRIDE + ky;
                    uint32_t ad = sb32 + (uint32_t)((((buf * R + row) * PXW) + pxbase + kx) * 16 + koff) * 2;
                    ldsm_x4(A[r][0], A[r][1], A[r][2], A[r][3], ad);
                }
#pragma unroll
                for (int r = 0; r < TM; r++)
#pragma unroll
                    for (int nt = 0; nt < NT; nt++)
                        mma16816(acc[r][nt], A[r], bh[nt].x, bh[nt].y);
            }
        }
        if (BUFS == 2) __syncthreads();
    }

    // epilogue
    const int xa = xb + mwarp * 16 + g;
#pragma unroll
    for (int r = 0; r < TM; r++) {
        const int y = y0 + r;
        const size_t pa = (size_t)(bb * OH + y) * OW + xa;
        const size_t pb = pa + 8;
        const float mva = mask[pa];
        const float mvb = mask[pb];
#pragma unroll
        for (int nt = 0; nt < NT; nt++) {
            const int co = nwarp * (COUT / 2) + nt * 8 + 2 * q;
            const float g0 = __ldg(gm + co), g1 = __ldg(gm + co + 1);
            const float b0 = __ldg(bt + co), b1 = __ldg(bt + co + 1);
            float v0 = acc[r][nt][0] * g0 + b0;
            float v1 = acc[r][nt][1] * g1 + b1;
            float v2 = acc[r][nt][2] * g0 + b0;
            float v3 = acc[r][nt][3] * g1 + b1;
            if (RESID) {
                float2 ra = *reinterpret_cast<const float2*>(resid + pa * COUT + co);
                float2 rb = *reinterpret_cast<const float2*>(resid + pb * COUT + co);
                v0 = fmaxf(ra.x + v0 * mva, 0.f);
                v1 = fmaxf(ra.y + v1 * mva, 0.f);
                v2 = fmaxf(rb.x + v2 * mvb, 0.f);
                v3 = fmaxf(rb.y + v3 * mvb, 0.f);
            } else {
                v0 = fmaxf(v0, 0.f) * mva;
                v1 = fmaxf(v1, 0.f) * mva;
                v2 = fmaxf(v2, 0.f) * mvb;
                v3 = fmaxf(v3, 0.f) * mvb;
            }
            if (OUTF32) {
                *reinterpret_cast<float2*>(outf + pa * COUT + co) = make_float2(v0, v1);
                *reinterpret_cast<float2*>(outf + pb * COUT + co) = make_float2(v2, v3);
            }
            if (PLANES) {
                *reinterpret_cast<uint32_t*>(outh + pa * COUT + co) = pack_h2(v0, v1);
                *reinterpret_cast<uint32_t*>(outh + pb * COUT + co) = pack_h2(v2, v3);
            }
        }
    }
}

// ---------------- bilinear gather (fp32) ----------------
__global__ __launch_bounds__(256) void gather_kernel(
    const float* __restrict__ feat, const int* __restrict__ unq, const int* __restrict__ inv,
    const float* __restrict__ xb2, float* __restrict__ out)
{
    int gwarp = (blockIdx.x * blockDim.x + threadIdx.x) >> 5;
    int lane = threadIdx.x & 31;
    if (gwarp >= NPTS) return;
    int i = gwarp;
    float f0 = __ldg(feat + (size_t)i * 16);
    float f1 = __ldg(feat + (size_t)i * 16 + 1);
    float px = ((f0 + 51.2f) / 0.4f) * 0.5f;
    float py = ((f1 + 51.2f) / 0.4f) * 0.5f;
    int seg = __ldg(inv + i);
    int bb = __ldg(unq + seg * 3);
    int fx = (int)floorf(px), fy = (int)floorf(py);
    int x0 = min(max(fx, 0), GS2 - 1), x1 = min(max(fx + 1, 0), GS2 - 1);
    int y0 = min(max(fy, 0), GS2 - 1), y1 = min(max(fy + 1, 0), GS2 - 1);
    float x0f = (float)x0, x1f = (float)x1, y0f = (float)y0, y1f = (float)y1;
    float wa = (x1f - px) * (y1f - py);
    float wb = (x1f - px) * (py - y0f);
    float wc = (px - x0f) * (y1f - py);
    float wd = (px - x0f) * (py - y0f);
    const float4* A  = reinterpret_cast<const float4*>(xb2 + ((size_t)(bb*GS2+y0)*GS2+x0)*C2) + lane;
    const float4* Bp = reinterpret_cast<const float4*>(xb2 + ((size_t)(bb*GS2+y1)*GS2+x0)*C2) + lane;
    const float4* Cp = reinterpret_cast<const float4*>(xb2 + ((size_t)(bb*GS2+y0)*GS2+x1)*C2) + lane;
    const float4* D  = reinterpret_cast<const float4*>(xb2 + ((size_t)(bb*GS2+y1)*GS2+x1)*C2) + lane;
    float4 a = __ldg(A), b = __ldg(Bp), c = __ldg(Cp), d = __ldg(D);
    float4 r;
    r.x = a.x*wa + b.x*wb + c.x*wc + d.x*wd;
    r.y = a.y*wa + b.y*wb + c.y*wc + d.y*wd;
    r.z = a.z*wa + b.z*wb + c.z*wc + d.z*wd;
    r.w = a.w*wa + b.w*wb + c.w*wc + d.w*wd;
    reinterpret_cast<float4*>(out + (size_t)i * C2)[lane] = r;
}

// ---------------- launch ----------------
extern "C" void kernel_launch(void* const* d_in, const int* in_sizes, int n_in,
                              void* d_out, int out_size)
{
    const float* feat = (const float*)d_in[0];
    const int* unq = (const int*)d_in[1];
    const int* inv = (const int*)d_in[2];
    int wb = (in_sizes[3] == 1) ? 4 : 3;
    const float* W[24];
    for (int i = 0; i < 24; i++) W[i] = (const float*)d_in[wb + i];
    float* out = (float*)d_out;

    float *p_h0, *p_hmax, *p_fv, *p_x1, *p_x2, *p_xb2, *p_occ, *p_occ1, *p_occ2;
    __half *a0, *a1, *a2, *a3, *a4, *a5;
    uint2* p_wf;
    cudaGetSymbolAddress((void**)&p_h0, g_h0);
    cudaGetSymbolAddress((void**)&p_hmax, g_hmax);
    cudaGetSymbolAddress((void**)&p_fv, g_fv);
    cudaGetSymbolAddress((void**)&p_x1, g_x1);
    cudaGetSymbolAddress((void**)&p_x2, g_x2);
    cudaGetSymbolAddress((void**)&p_xb2, g_xb2);
    cudaGetSymbolAddress((void**)&p_occ, g_occ);
    cudaGetSymbolAddress((void**)&p_occ1, g_occ1);
    cudaGetSymbolAddress((void**)&p_occ2, g_occ2);
    cudaGetSymbolAddress((void**)&a0, g_a0);
    cudaGetSymbolAddress((void**)&a1, g_a1);
    cudaGetSymbolAddress((void**)&a2, g_a2);
    cudaGetSymbolAddress((void**)&a3, g_a3);
    cudaGetSymbolAddress((void**)&a4, g_a4);
    cudaGetSymbolAddress((void**)&a5, g_a5);
    cudaGetSymbolAddress((void**)&p_wf, g_wfrag);

    const int N0 = BATCH*GS*GS*C1*2/16;
    const int N1 = MPIL*16*4/16;
    const int N2 = MPIL*64*4/16;
    const int N3 = BATCH*GS*GS*4/16;
    zero_all_kernel<<<(N0+N1+N2+N3 + 255)/256, 256>>>(
        (uint4*)a0, N0, (uint4*)p_hmax, N1, (uint4*)p_fv, N2, (uint4*)p_occ, N3);

    wprep_all_kernel<<<(119808 + 255)/256, 256>>>(
        W[6], W[9], W[12], W[15], W[18], W[21], p_wf);

    pfn0_kernel<<<(NPTS + 255)/256, 256>>>(feat, inv, W[0], W[1], W[2], p_h0, p_hmax);
    pfn1_kernel<<<(NPTS + 127)/128, 128>>>(inv, W[3], W[4], W[5], p_h0, p_hmax, p_fv);
    scatter_kernel<<<(MPIL*8 + 255)/256, 256>>>(unq, p_fv, a0, p_occ);
    occ12_kernel<<<(BATCH*GS*GS + BATCH*GS2*GS2 + 255)/256, 256>>>(p_occ, p_occ1, p_occ2);

    const int S13 = 3 * 6 * 66 * 16 * 2;   // 38016
    const int S4  = 3 * 5 * 130 * 16 * 2;  // 62400
    const int S56 = 3 * 4 * 66 * 16 * 2;   // 25344
    cudaFuncSetAttribute(conv_mma<64,64,1,4,3,false,true,true>,   cudaFuncAttributeMaxDynamicSharedMemorySize, S13);
    cudaFuncSetAttribute(conv_mma<64,64,1,4,3,false,false,true>,  cudaFuncAttributeMaxDynamicSharedMemorySize, S13);
    cudaFuncSetAttribute(conv_mma<64,64,1,4,3,true,false,true>,   cudaFuncAttributeMaxDynamicSharedMemorySize, S13);
    cudaFuncSetAttribute(conv_mma<64,128,2,2,3,false,true,true>,  cudaFuncAttributeMaxDynamicSharedMemorySize, S4);
    cudaFuncSetAttribute(conv_mma<128,128,1,2,3,false,false,true>,cudaFuncAttributeMaxDynamicSharedMemorySize, S56);
    cudaFuncSetAttribute(conv_mma<128,128,1,2,3,true,true,false>, cudaFuncAttributeMaxDynamicSharedMemorySize, S56);

    dim3 blk(256);
    dim3 g1(GS/64, GS/4, BATCH);
    conv_mma<64,64,1,4,3,false,true,true><<<g1, blk, S13>>>(
        a0, p_wf + FOFF1, W[7], W[8], p_occ1, nullptr, p_x1, a1, GS, GS, GS, GS);
    conv_mma<64,64,1,4,3,false,false,true><<<g1, blk, S13>>>(
        a1, p_wf + FOFF2, W[10], W[11], p_occ1, nullptr, nullptr, a2, GS, GS, GS, GS);
    conv_mma<64,64,1,4,3,true,false,true><<<g1, blk, S13>>>(
        a2, p_wf + FOFF3, W[13], W[14], p_occ1, p_x1, nullptr, a3, GS, GS, GS, GS);

    dim3 g2(GS2/64, GS2/2, BATCH);
    conv_mma<64,128,2,2,3,false,true,true><<<g2, blk, S4>>>(
        a3, p_wf + FOFF4, W[16], W[17], p_occ2, nullptr, p_x2, a4, GS, GS, GS2, GS2);
    conv_mma<128,128,1,2,3,false,false,true><<<g2, blk, S56>>>(
        a4, p_wf + FOFF5, W[19], W[20], p_occ2, nullptr, nullptr, a5, GS2, GS2, GS2, GS2);
    conv_mma<128,128,1,2,3,true,true,false><<<g2, blk, S56>>>(
        a5, p_wf + FOFF6, W[22], W[23], p_occ2, p_x2, p_xb2, nullptr, GS2, GS2, GS2, GS2);

    gather_kernel<<<(NPTS*32 + 255)/256, 256>>>(feat, unq, inv, p_xb2, out);
    (void)n_in; (void)out_size;
}